// round 2
// baseline (speedup 1.0000x reference)
#include <cuda_runtime.h>

#define NMAX 100000
#define EMAX 1000000
#define CAP 96
#define OVF_CAP 8192

// ---------------- scratch (no allocations allowed) ----------------
__device__ float g_h1[NMAX * 64];    // lin1 output
__device__ float g_agg1[NMAX * 64];  // layer-1 aggregation
__device__ float g_t1[NMAX * 64];    // mid-MLP temp
__device__ float g_h2[NMAX * 40];    // lin2 output
__device__ float g_agg2[NMAX * 40];  // layer-2 aggregation
__device__ int   g_deg[NMAX];        // per-dst degree counters
__device__ int   g_col[(size_t)NMAX * CAP]; // bucketed CSR columns (src per dst)
__device__ int   g_ovf_cnt;
__device__ int   g_ovf_src[OVF_CAP];
__device__ int   g_ovf_dst[OVF_CAP];
__device__ int   g_idx32;            // 1 if edge_index is int32, 0 if int64

__device__ __forceinline__ void red_add_f4(float* p, float4 v) {
    asm volatile("red.global.add.v4.f32 [%0], {%1,%2,%3,%4};"
                 :: "l"(p), "f"(v.x), "f"(v.y), "f"(v.z), "f"(v.w)
                 : "memory");
}

// ---------------- dtype probe: int64 vs int32 edge_index ----------------
__global__ void detect_idx_kernel(const long long* __restrict__ idx, int E, long long N) {
    if (blockIdx.x == 0 && threadIdx.x == 0) {
        int is32 = 0;
        int nc = E < 64 ? E : 64;
        for (int i = 0; i < nc; i++) {
            long long v = idx[i];
            if (v < 0 || v >= N) { is32 = 1; break; }
        }
        g_idx32 = is32;
    }
}

// ---------------- zero counters ----------------
__global__ void zero_deg_kernel(int N) {
    int i = blockIdx.x * blockDim.x + threadIdx.x;
    if (i < N) g_deg[i] = 0;
    if (i == 0) g_ovf_cnt = 0;
}

// ---------------- CSR bucket fill ----------------
__global__ void csr_fill_kernel(const long long* __restrict__ idx, int E) {
    int e = blockIdx.x * blockDim.x + threadIdx.x;
    if (e >= E) return;
    int s, d;
    if (g_idx32) {
        const int* p = (const int*)idx;
        s = p[e]; d = p[E + e];
    } else {
        s = (int)idx[e]; d = (int)idx[E + e];
    }
    int slot = atomicAdd(&g_deg[d], 1);
    if (slot < CAP) {
        g_col[(size_t)d * CAP + slot] = s;
    } else {
        int o = atomicAdd(&g_ovf_cnt, 1);
        if (o < OVF_CAP) { g_ovf_src[o] = s; g_ovf_dst[o] = d; }
    }
}

// ---------------- gather: AGG[n] = H[n] + sum_j H[col[n][j]] ----------------
// warp per node, lane owns 2 features (F=64: 32 lanes; F=40: 20 lanes)
template<int F>
__global__ void gather_kernel(const float* __restrict__ H, float* __restrict__ AGG, int N) {
    int warp = (int)((blockIdx.x * (long long)blockDim.x + threadIdx.x) >> 5);
    int lane = threadIdx.x & 31;
    if (warp >= N) return;
    constexpr int L = F / 2;   // active lanes
    bool act = lane < L;
    float2 acc = make_float2(0.f, 0.f);
    if (act) acc = *(const float2*)&H[(size_t)warp * F + lane * 2];   // self-loop term
    int deg = g_deg[warp];
    if (deg > CAP) deg = CAP;
    const int* cp = g_col + (size_t)warp * CAP;
    int j = 0;
    for (; j + 4 <= deg; j += 4) {
        int4 s = *(const int4*)&cp[j];
        float2 v0 = make_float2(0.f,0.f), v1 = v0, v2 = v0, v3 = v0;
        if (act) {
            v0 = *(const float2*)&H[(size_t)s.x * F + lane * 2];
            v1 = *(const float2*)&H[(size_t)s.y * F + lane * 2];
            v2 = *(const float2*)&H[(size_t)s.z * F + lane * 2];
            v3 = *(const float2*)&H[(size_t)s.w * F + lane * 2];
        }
        acc.x += (v0.x + v1.x) + (v2.x + v3.x);
        acc.y += (v0.y + v1.y) + (v2.y + v3.y);
    }
    for (; j < deg; j++) {
        int s = cp[j];
        if (act) {
            float2 v = *(const float2*)&H[(size_t)s * F + lane * 2];
            acc.x += v.x; acc.y += v.y;
        }
    }
    if (act) *(float2*)&AGG[(size_t)warp * F + lane * 2] = acc;
}

// ---------------- overflow scatter (expected count: 0) ----------------
template<int F>
__global__ void ovf_scatter_kernel(const float* __restrict__ H, float* __restrict__ AGG) {
    int cnt = g_ovf_cnt;
    if (cnt > OVF_CAP) cnt = OVF_CAP;
    int total = cnt * (F / 4);
    for (int i = blockIdx.x * blockDim.x + threadIdx.x; i < total;
         i += gridDim.x * blockDim.x) {
        int e = i / (F / 4);
        int q = (i - e * (F / 4)) * 4;
        int s = g_ovf_src[e], d = g_ovf_dst[e];
        float4 v = *(const float4*)&H[(size_t)s * F + q];
        red_add_f4(&AGG[(size_t)d * F + q], v);
    }
}

// ---------------- generic node-parallel GEMM: Y = [relu](X[relu] @ W^T + b) ----------------
// Tile: 128 nodes x NF feats. Thread = (tx feat-quad, ty node-group-of-4).
// X staged transposed in smem (k-major) so activation loads are LDS.128 over 4 nodes.
// In-place (Y == X) is safe for single-K-chunk instantiations: each block reads
// only its own 128 rows into smem before writing them.
template<int KIN, int NF, int THREADS, bool RIN, bool ROUT>
__global__ void __launch_bounds__(THREADS, 1024 / THREADS)
gemm_kernel(const float* __restrict__ X, const float* __restrict__ W,
            const float* __restrict__ b, float* __restrict__ Y, int N)
{
    constexpr int QX = NF / 4;            // feat quads (16 or 10)
    constexpr int GY = THREADS / QX;      // node groups (32)
    constexpr int TN = GY * 4;            // nodes per block (128)
    constexpr int KC = (KIN > 64) ? 64 : KIN;
    constexpr int NCH = KIN / KC;
    constexpr int WP = NF + 4;            // padded W row (68 / 44)
    constexpr int XP = 132;               // padded XT row

    extern __shared__ float sm[];
    float* sW  = sm;                      // sW[k*WP + f], full K resident
    float* sXT = sm + KIN * WP;           // sXT[kk*XP + n], one K-chunk

    int t = threadIdx.x;
    int n0 = blockIdx.x * TN;

    // load W [NF][KIN] row-major -> k-major smem
    for (int i = t; i < NF * KIN; i += THREADS) {
        int f = i / KIN, k = i - f * KIN;
        sW[k * WP + f] = W[i];
    }

    int tx = t % QX, ty = t / QX;
    int fq = tx * 4;
    int nb = ty * 4;

    float acc[4][4];
#pragma unroll
    for (int m = 0; m < 4; m++)
#pragma unroll
        for (int j = 0; j < 4; j++) acc[m][j] = 0.f;

    for (int ch = 0; ch < NCH; ch++) {
        int k0 = ch * KC;
        __syncthreads();
        // load X chunk transposed (coalesced global read)
        for (int i = t; i < TN * KC; i += THREADS) {
            int n = i / KC, kk = i - n * KC;
            int gn = n0 + n;
            float v = (gn < N) ? X[(size_t)gn * KIN + k0 + kk] : 0.f;
            if (RIN) v = fmaxf(v, 0.f);
            sXT[kk * XP + n] = v;
        }
        __syncthreads();

#pragma unroll 4
        for (int kk = 0; kk < KC; kk++) {
            float4 wq = *(const float4*)&sW[(k0 + kk) * WP + fq];
            float4 xv = *(const float4*)&sXT[kk * XP + nb];
            acc[0][0] += xv.x * wq.x; acc[0][1] += xv.x * wq.y;
            acc[0][2] += xv.x * wq.z; acc[0][3] += xv.x * wq.w;
            acc[1][0] += xv.y * wq.x; acc[1][1] += xv.y * wq.y;
            acc[1][2] += xv.y * wq.z; acc[1][3] += xv.y * wq.w;
            acc[2][0] += xv.z * wq.x; acc[2][1] += xv.z * wq.y;
            acc[2][2] += xv.z * wq.z; acc[2][3] += xv.z * wq.w;
            acc[3][0] += xv.w * wq.x; acc[3][1] += xv.w * wq.y;
            acc[3][2] += xv.w * wq.z; acc[3][3] += xv.w * wq.w;
        }
    }

    float b0 = __ldg(b + fq + 0), b1 = __ldg(b + fq + 1);
    float b2 = __ldg(b + fq + 2), b3 = __ldg(b + fq + 3);
#pragma unroll
    for (int m = 0; m < 4; m++) {
        int gn = n0 + nb + m;
        if (gn < N) {
            float4 v = make_float4(acc[m][0] + b0, acc[m][1] + b1,
                                   acc[m][2] + b2, acc[m][3] + b3);
            if (ROUT) {
                v.x = fmaxf(v.x, 0.f); v.y = fmaxf(v.y, 0.f);
                v.z = fmaxf(v.z, 0.f); v.w = fmaxf(v.w, 0.f);
            }
            *(float4*)&Y[(size_t)gn * NF + fq] = v;
        }
    }
}

// ---------------- launch ----------------
extern "C" void kernel_launch(void* const* d_in, const int* in_sizes, int n_in,
                              void* d_out, int out_size) {
    const float*     x   = (const float*)d_in[0];
    const long long* idx = (const long long*)d_in[1];
    const float* w1_lin = (const float*)d_in[2];
    const float* b1_lin = (const float*)d_in[3];
    const float* w1_o1  = (const float*)d_in[4];
    const float* b1_o1  = (const float*)d_in[5];
    const float* w1_o2  = (const float*)d_in[6];
    const float* b1_o2  = (const float*)d_in[7];
    const float* w2_lin = (const float*)d_in[8];
    const float* b2_lin = (const float*)d_in[9];
    const float* w2_o1  = (const float*)d_in[10];
    const float* b2_o1  = (const float*)d_in[11];
    const float* w2_o2  = (const float*)d_in[12];
    const float* b2_o2  = (const float*)d_in[13];
    float* out = (float*)d_out;

    int N = in_sizes[0] / 128;
    int E = in_sizes[1] / 2;

    // smem sizes per instantiation
    const size_t SM_LIN1 = (size_t)(128 * 68 + 64 * 132) * 4;  // 68608
    const size_t SM_S64  = (size_t)(64 * 68 + 64 * 132) * 4;   // 51200
    const size_t SM_LIN2 = (size_t)(64 * 44 + 64 * 132) * 4;   // 45056
    const size_t SM_S40  = (size_t)(40 * 44 + 40 * 132) * 4;   // 28160

    cudaFuncSetAttribute((const void*)gemm_kernel<128,64,512,false,false>,
                         cudaFuncAttributeMaxDynamicSharedMemorySize, (int)SM_LIN1);
    cudaFuncSetAttribute((const void*)gemm_kernel<64,64,512,true,true>,
                         cudaFuncAttributeMaxDynamicSharedMemorySize, (int)SM_S64);
    cudaFuncSetAttribute((const void*)gemm_kernel<64,64,512,false,true>,
                         cudaFuncAttributeMaxDynamicSharedMemorySize, (int)SM_S64);
    cudaFuncSetAttribute((const void*)gemm_kernel<64,40,320,false,false>,
                         cudaFuncAttributeMaxDynamicSharedMemorySize, (int)SM_LIN2);
    cudaFuncSetAttribute((const void*)gemm_kernel<40,40,320,true,true>,
                         cudaFuncAttributeMaxDynamicSharedMemorySize, (int)SM_S40);
    cudaFuncSetAttribute((const void*)gemm_kernel<40,40,320,false,false>,
                         cudaFuncAttributeMaxDynamicSharedMemorySize, (int)SM_S40);

    int nodeBlocks = (N + 127) / 128;

    // CSR build
    detect_idx_kernel<<<1, 32>>>(idx, E, (long long)N);
    zero_deg_kernel<<<(N + 255) / 256, 256>>>(N);
    csr_fill_kernel<<<(E + 255) / 256, 256>>>(idx, E);

    // layer 1
    gemm_kernel<128,64,512,false,false><<<nodeBlocks, 512, SM_LIN1>>>(x, w1_lin, b1_lin, g_h1, N);
    gather_kernel<64><<<(N + 7) / 8, 256>>>(g_h1, g_agg1, N);
    ovf_scatter_kernel<64><<<64, 128>>>(g_h1, g_agg1);
    gemm_kernel<64,64,512,true,true ><<<nodeBlocks, 512, SM_S64>>>(g_agg1, w1_o1, b1_o1, g_t1, N);
    gemm_kernel<64,64,512,false,true><<<nodeBlocks, 512, SM_S64>>>(g_t1, w1_o2, b1_o2, g_t1, N);

    // layer 2
    gemm_kernel<64,40,320,false,false><<<nodeBlocks, 320, SM_LIN2>>>(g_t1, w2_lin, b2_lin, g_h2, N);
    gather_kernel<40><<<(N + 7) / 8, 256>>>(g_h2, g_agg2, N);
    ovf_scatter_kernel<40><<<64, 128>>>(g_h2, g_agg2);
    gemm_kernel<40,40,320,true,true  ><<<nodeBlocks, 320, SM_S40>>>(g_agg2, w2_o1, b2_o1, g_agg2, N);
    gemm_kernel<40,40,320,false,false><<<nodeBlocks, 320, SM_S40>>>(g_agg2, w2_o2, b2_o2, out, N);
}

// round 5
// speedup vs baseline: 11.0987x; 11.0987x over previous
#include <cuda_runtime.h>

#define NMAX 100000
#define EMAX 1000000
#define CAP 96
#define OVF_CAP 8192

// ---------------- scratch (no allocations allowed) ----------------
// NOTE: these symbols are ONLY ever referenced from device code. Passing a
// __device__ symbol as a kernel argument from host code silently binds the
// HOST shadow address (GB300 ATS makes it dereferenceable!) — that was the
// R2 slowdown / R3-R4 zero-output bug.
__device__ float g_h1[NMAX * 64];    // lin1 output
__device__ float g_agg1[NMAX * 64];  // aggregation target layer 1
__device__ float g_h2[NMAX * 40];    // lin2 output (after mid-MLP)
__device__ float g_agg2[NMAX * 40];  // aggregation target layer 2
__device__ int   g_deg[NMAX];        // per-dst degree counters
__device__ int   g_col[(size_t)NMAX * CAP]; // bucketed adjacency (src per dst)
__device__ int   g_ovf_cnt;
__device__ int   g_ovf_src[OVF_CAP];
__device__ int   g_ovf_dst[OVF_CAP];
__device__ int   g_idx32;            // 1 if edge_index is int32, 0 if int64

__device__ __forceinline__ void red_add_f4(float* p, float4 v) {
    asm volatile("red.global.add.v4.f32 [%0], {%1,%2,%3,%4};"
                 :: "l"(p), "f"(v.x), "f"(v.y), "f"(v.z), "f"(v.w)
                 : "memory");
}

// ---------------- dtype probe: int64 vs int32 edge_index ----------------
__global__ void detect_idx_kernel(const long long* __restrict__ idx, int E, long long N) {
    if (blockIdx.x == 0 && threadIdx.x == 0) {
        int is32 = 0;
        int nc = E < 64 ? E : 64;
        for (int i = 0; i < nc; i++) {
            long long v = idx[i];
            if (v < 0 || v >= N) { is32 = 1; break; }
        }
        g_idx32 = is32;
    }
}

// ---------------- zero counters ----------------
__global__ void zero_deg_kernel(int N) {
    int i = blockIdx.x * blockDim.x + threadIdx.x;
    if (i < N) g_deg[i] = 0;
    if (i == 0) g_ovf_cnt = 0;
}

// ---------------- CSR bucket fill ----------------
__global__ void csr_fill_kernel(const long long* __restrict__ idx, int E) {
    int e = blockIdx.x * blockDim.x + threadIdx.x;
    if (e >= E) return;
    int s, d;
    if (g_idx32) {
        const int* p = (const int*)idx;
        s = p[e]; d = p[E + e];
    } else {
        s = (int)idx[e]; d = (int)idx[E + e];
    }
    int slot = atomicAdd(&g_deg[d], 1);
    if (slot < CAP) {
        g_col[(size_t)d * CAP + slot] = s;
    } else {
        int o = atomicAdd(&g_ovf_cnt, 1);
        if (o < OVF_CAP) { g_ovf_src[o] = s; g_ovf_dst[o] = d; }
    }
}

// ---------------- gather: AGG[n] = H[n] + sum_j H[col[n][j]] ----------------
// warp per node, lane owns 2 features. Buffers selected in DEVICE code via
// LAYER template param (never passed from host).
template<int F, int LAYER>
__global__ void gather_kernel(int N) {
    const float* __restrict__ H   = (LAYER == 1) ? g_h1   : g_h2;
    float* __restrict__       AGG = (LAYER == 1) ? g_agg1 : g_agg2;
    int warp = (int)((blockIdx.x * (long long)blockDim.x + threadIdx.x) >> 5);
    int lane = threadIdx.x & 31;
    if (warp >= N) return;
    constexpr int L = F / 2;   // active lanes
    bool act = lane < L;
    float2 acc = make_float2(0.f, 0.f);
    if (act) acc = *(const float2*)&H[(size_t)warp * F + lane * 2];   // self-loop term
    int deg = g_deg[warp];
    if (deg > CAP) deg = CAP;
    const int* cp = g_col + (size_t)warp * CAP;
    int j = 0;
    for (; j + 4 <= deg; j += 4) {
        int4 s = *(const int4*)&cp[j];
        float2 v0 = make_float2(0.f,0.f), v1 = v0, v2 = v0, v3 = v0;
        if (act) {
            v0 = *(const float2*)&H[(size_t)s.x * F + lane * 2];
            v1 = *(const float2*)&H[(size_t)s.y * F + lane * 2];
            v2 = *(const float2*)&H[(size_t)s.z * F + lane * 2];
            v3 = *(const float2*)&H[(size_t)s.w * F + lane * 2];
        }
        acc.x += (v0.x + v1.x) + (v2.x + v3.x);
        acc.y += (v0.y + v1.y) + (v2.y + v3.y);
    }
    for (; j < deg; j++) {
        int s = cp[j];
        if (act) {
            float2 v = *(const float2*)&H[(size_t)s * F + lane * 2];
            acc.x += v.x; acc.y += v.y;
        }
    }
    if (act) *(float2*)&AGG[(size_t)warp * F + lane * 2] = acc;
}

// ---------------- overflow scatter (expected count: 0) ----------------
template<int F, int LAYER>
__global__ void ovf_scatter_kernel() {
    const float* __restrict__ H   = (LAYER == 1) ? g_h1   : g_h2;
    float* __restrict__       AGG = (LAYER == 1) ? g_agg1 : g_agg2;
    int cnt = g_ovf_cnt;
    if (cnt > OVF_CAP) cnt = OVF_CAP;
    int total = cnt * (F / 4);
    for (int i = blockIdx.x * blockDim.x + threadIdx.x; i < total;
         i += gridDim.x * blockDim.x) {
        int e = i / (F / 4);
        int q = (i - e * (F / 4)) * 4;
        int s = g_ovf_src[e], d = g_ovf_dst[e];
        float4 v = *(const float4*)&H[(size_t)s * F + q];
        red_add_f4(&AGG[(size_t)d * F + q], v);
    }
}

// ---------------- K1: h = x @ W1^T + b1  (128 -> 64)  [R1 verbatim, minus agg dup] ----------------
__global__ void lin1_kernel(const float* __restrict__ x, const float* __restrict__ W,
                            const float* __restrict__ b, int N) {
    extern __shared__ float sm[];
    float* sW = sm;             // sW[k*65 + f], k<128, f<64
    float* sx = sm + 128 * 65;  // sx[n*129 + k], n<64, k<128
    int t = threadIdx.x;

    for (int i = t; i < 64 * 128; i += 128) {
        int f = i >> 7, k = i & 127;          // W row-major [64][128]
        sW[k * 65 + f] = W[i];
    }
    int n0 = blockIdx.x * 64;
    for (int i = t; i < 64 * 128; i += 128) {
        int n = i >> 7, k = i & 127;
        int gn = n0 + n;
        sx[n * 129 + k] = (gn < N) ? x[(long long)gn * 128 + k] : 0.f;
    }
    __syncthreads();

    int fq = (t & 15) * 4;
    int ng = (t >> 4) * 8;
    float acc[8][4];
#pragma unroll
    for (int m = 0; m < 8; m++)
#pragma unroll
        for (int j = 0; j < 4; j++) acc[m][j] = 0.f;

#pragma unroll 4
    for (int k = 0; k < 128; k++) {
        float w0 = sW[k * 65 + fq + 0];
        float w1 = sW[k * 65 + fq + 1];
        float w2 = sW[k * 65 + fq + 2];
        float w3 = sW[k * 65 + fq + 3];
#pragma unroll
        for (int m = 0; m < 8; m++) {
            float xv = sx[(ng + m) * 129 + k];
            acc[m][0] += xv * w0; acc[m][1] += xv * w1;
            acc[m][2] += xv * w2; acc[m][3] += xv * w3;
        }
    }
    float b0 = __ldg(b + fq + 0), b1 = __ldg(b + fq + 1);
    float b2 = __ldg(b + fq + 2), b3 = __ldg(b + fq + 3);
#pragma unroll
    for (int m = 0; m < 8; m++) {
        int gn = n0 + ng + m;
        if (gn < N) {
            float4 v = make_float4(acc[m][0] + b0, acc[m][1] + b1,
                                   acc[m][2] + b2, acc[m][3] + b3);
            *(float4*)(g_h1 + (long long)gn * 64 + fq) = v;
        }
    }
}

// ---------------- K3: fused mid-MLP  [R1 verbatim, minus agg dup] ----------------
__global__ void mlp1_kernel(const float* __restrict__ Wo1, const float* __restrict__ bo1,
                            const float* __restrict__ Wo2, const float* __restrict__ bo2,
                            const float* __restrict__ W2l, const float* __restrict__ b2l,
                            int N) {
    extern __shared__ float sm[];
    float* sW1 = sm;                  // [k*65+f] k<64 f<64
    float* sW2 = sW1 + 64 * 65;
    float* sW3 = sW2 + 64 * 65;       // [k*40+f] k<64 f<40
    float* sA  = sW3 + 64 * 40;       // [n*65+k]
    float* sB  = sA  + 64 * 65;
    int t = threadIdx.x;

    for (int i = t; i < 64 * 64; i += 128) {
        int f = i >> 6, k = i & 63;
        sW1[k * 65 + f] = Wo1[i];
        sW2[k * 65 + f] = Wo2[i];
    }
    for (int i = t; i < 40 * 64; i += 128) {
        int f = i >> 6, k = i & 63;   // W2l row-major [40][64]
        sW3[k * 40 + f] = W2l[i];
    }
    int n0 = blockIdx.x * 64;
    for (int i = t; i < 64 * 64; i += 128) {
        int n = i >> 6, k = i & 63;
        int gn = n0 + n;
        float v = (gn < N) ? g_agg1[(long long)gn * 64 + k] : 0.f;
        sA[n * 65 + k] = fmaxf(v, 0.f);
    }
    __syncthreads();

    int fq = (t & 15) * 4;
    int ng = (t >> 4) * 8;

    // stage 1: sB = relu(sA @ Wo1^T + bo1)
    {
        float acc[8][4];
#pragma unroll
        for (int m = 0; m < 8; m++)
#pragma unroll
            for (int j = 0; j < 4; j++) acc[m][j] = 0.f;
#pragma unroll 4
        for (int k = 0; k < 64; k++) {
            float w0 = sW1[k * 65 + fq + 0];
            float w1 = sW1[k * 65 + fq + 1];
            float w2 = sW1[k * 65 + fq + 2];
            float w3 = sW1[k * 65 + fq + 3];
#pragma unroll
            for (int m = 0; m < 8; m++) {
                float xv = sA[(ng + m) * 65 + k];
                acc[m][0] += xv * w0; acc[m][1] += xv * w1;
                acc[m][2] += xv * w2; acc[m][3] += xv * w3;
            }
        }
        float c0 = __ldg(bo1 + fq + 0), c1 = __ldg(bo1 + fq + 1);
        float c2 = __ldg(bo1 + fq + 2), c3 = __ldg(bo1 + fq + 3);
#pragma unroll
        for (int m = 0; m < 8; m++) {
            sB[(ng + m) * 65 + fq + 0] = fmaxf(acc[m][0] + c0, 0.f);
            sB[(ng + m) * 65 + fq + 1] = fmaxf(acc[m][1] + c1, 0.f);
            sB[(ng + m) * 65 + fq + 2] = fmaxf(acc[m][2] + c2, 0.f);
            sB[(ng + m) * 65 + fq + 3] = fmaxf(acc[m][3] + c3, 0.f);
        }
    }
    __syncthreads();

    // stage 2: sA = relu(sB @ Wo2^T + bo2)
    {
        float acc[8][4];
#pragma unroll
        for (int m = 0; m < 8; m++)
#pragma unroll
            for (int j = 0; j < 4; j++) acc[m][j] = 0.f;
#pragma unroll 4
        for (int k = 0; k < 64; k++) {
            float w0 = sW2[k * 65 + fq + 0];
            float w1 = sW2[k * 65 + fq + 1];
            float w2 = sW2[k * 65 + fq + 2];
            float w3 = sW2[k * 65 + fq + 3];
#pragma unroll
            for (int m = 0; m < 8; m++) {
                float xv = sB[(ng + m) * 65 + k];
                acc[m][0] += xv * w0; acc[m][1] += xv * w1;
                acc[m][2] += xv * w2; acc[m][3] += xv * w3;
            }
        }
        float c0 = __ldg(bo2 + fq + 0), c1 = __ldg(bo2 + fq + 1);
        float c2 = __ldg(bo2 + fq + 2), c3 = __ldg(bo2 + fq + 3);
        __syncthreads();
#pragma unroll
        for (int m = 0; m < 8; m++) {
            sA[(ng + m) * 65 + fq + 0] = fmaxf(acc[m][0] + c0, 0.f);
            sA[(ng + m) * 65 + fq + 1] = fmaxf(acc[m][1] + c1, 0.f);
            sA[(ng + m) * 65 + fq + 2] = fmaxf(acc[m][2] + c2, 0.f);
            sA[(ng + m) * 65 + fq + 3] = fmaxf(acc[m][3] + c3, 0.f);
        }
    }
    __syncthreads();

    // stage 3: h2 = sA @ W2l^T + b2l  (64 -> 40), write g_h2
    if ((t & 15) < 10) {
        float acc[8][4];
#pragma unroll
        for (int m = 0; m < 8; m++)
#pragma unroll
            for (int j = 0; j < 4; j++) acc[m][j] = 0.f;
#pragma unroll 4
        for (int k = 0; k < 64; k++) {
            float w0 = sW3[k * 40 + fq + 0];
            float w1 = sW3[k * 40 + fq + 1];
            float w2 = sW3[k * 40 + fq + 2];
            float w3 = sW3[k * 40 + fq + 3];
#pragma unroll
            for (int m = 0; m < 8; m++) {
                float xv = sA[(ng + m) * 65 + k];
                acc[m][0] += xv * w0; acc[m][1] += xv * w1;
                acc[m][2] += xv * w2; acc[m][3] += xv * w3;
            }
        }
        float c0 = __ldg(b2l + fq + 0), c1 = __ldg(b2l + fq + 1);
        float c2 = __ldg(b2l + fq + 2), c3 = __ldg(b2l + fq + 3);
#pragma unroll
        for (int m = 0; m < 8; m++) {
            int gn = n0 + ng + m;
            if (gn < N) {
                float4 v = make_float4(acc[m][0] + c0, acc[m][1] + c1,
                                       acc[m][2] + c2, acc[m][3] + c3);
                *(float4*)(g_h2 + (long long)gn * 40 + fq) = v;
            }
        }
    }
}

// ---------------- K5: final MLP  [R1 verbatim] ----------------
__global__ void mlp2_kernel(const float* __restrict__ Wo1, const float* __restrict__ bo1,
                            const float* __restrict__ Wo2, const float* __restrict__ bo2,
                            float* __restrict__ out, int N) {
    __shared__ float sW1[40 * 40];   // [k*40+f]
    __shared__ float sW2[40 * 40];
    __shared__ float sA[64 * 41];    // [n*41+k] k<40
    __shared__ float sB[64 * 41];
    int t = threadIdx.x;

    for (int i = t; i < 1600; i += 128) {
        int f = i / 40, k = i - f * 40;
        sW1[k * 40 + f] = Wo1[i];
        sW2[k * 40 + f] = Wo2[i];
    }
    int n0 = blockIdx.x * 64;
    for (int i = t; i < 64 * 40; i += 128) {
        int n = i / 40, k = i - n * 40;
        int gn = n0 + n;
        float v = (gn < N) ? g_agg2[(long long)gn * 40 + k] : 0.f;
        sA[n * 41 + k] = fmaxf(v, 0.f);
    }
    __syncthreads();

    int fq = (t & 15) * 4;
    int ng = (t >> 4) * 8;

    if ((t & 15) < 10) {
        float acc[8][4];
#pragma unroll
        for (int m = 0; m < 8; m++)
#pragma unroll
            for (int j = 0; j < 4; j++) acc[m][j] = 0.f;
#pragma unroll 4
        for (int k = 0; k < 40; k++) {
            float w0 = sW1[k * 40 + fq + 0];
            float w1 = sW1[k * 40 + fq + 1];
            float w2 = sW1[k * 40 + fq + 2];
            float w3 = sW1[k * 40 + fq + 3];
#pragma unroll
            for (int m = 0; m < 8; m++) {
                float xv = sA[(ng + m) * 41 + k];
                acc[m][0] += xv * w0; acc[m][1] += xv * w1;
                acc[m][2] += xv * w2; acc[m][3] += xv * w3;
            }
        }
        float c0 = __ldg(bo1 + fq + 0), c1 = __ldg(bo1 + fq + 1);
        float c2 = __ldg(bo1 + fq + 2), c3 = __ldg(bo1 + fq + 3);
#pragma unroll
        for (int m = 0; m < 8; m++) {
            sB[(ng + m) * 41 + fq + 0] = fmaxf(acc[m][0] + c0, 0.f);
            sB[(ng + m) * 41 + fq + 1] = fmaxf(acc[m][1] + c1, 0.f);
            sB[(ng + m) * 41 + fq + 2] = fmaxf(acc[m][2] + c2, 0.f);
            sB[(ng + m) * 41 + fq + 3] = fmaxf(acc[m][3] + c3, 0.f);
        }
    }
    __syncthreads();

    if ((t & 15) < 10) {
        float acc[8][4];
#pragma unroll
        for (int m = 0; m < 8; m++)
#pragma unroll
            for (int j = 0; j < 4; j++) acc[m][j] = 0.f;
#pragma unroll 4
        for (int k = 0; k < 40; k++) {
            float w0 = sW2[k * 40 + fq + 0];
            float w1 = sW2[k * 40 + fq + 1];
            float w2 = sW2[k * 40 + fq + 2];
            float w3 = sW2[k * 40 + fq + 3];
#pragma unroll
            for (int m = 0; m < 8; m++) {
                float xv = sB[(ng + m) * 41 + k];
                acc[m][0] += xv * w0; acc[m][1] += xv * w1;
                acc[m][2] += xv * w2; acc[m][3] += xv * w3;
            }
        }
        float c0 = __ldg(bo2 + fq + 0), c1 = __ldg(bo2 + fq + 1);
        float c2 = __ldg(bo2 + fq + 2), c3 = __ldg(bo2 + fq + 3);
#pragma unroll
        for (int m = 0; m < 8; m++) {
            int gn = n0 + ng + m;
            if (gn < N) {
                out[(long long)gn * 40 + fq + 0] = acc[m][0] + c0;
                out[(long long)gn * 40 + fq + 1] = acc[m][1] + c1;
                out[(long long)gn * 40 + fq + 2] = acc[m][2] + c2;
                out[(long long)gn * 40 + fq + 3] = acc[m][3] + c3;
            }
        }
    }
}

// ---------------- launch ----------------
extern "C" void kernel_launch(void* const* d_in, const int* in_sizes, int n_in,
                              void* d_out, int out_size) {
    const float*     x   = (const float*)d_in[0];
    const long long* idx = (const long long*)d_in[1];
    const float* w1_lin = (const float*)d_in[2];
    const float* b1_lin = (const float*)d_in[3];
    const float* w1_o1  = (const float*)d_in[4];
    const float* b1_o1  = (const float*)d_in[5];
    const float* w1_o2  = (const float*)d_in[6];
    const float* b1_o2  = (const float*)d_in[7];
    const float* w2_lin = (const float*)d_in[8];
    const float* b2_lin = (const float*)d_in[9];
    const float* w2_o1  = (const float*)d_in[10];
    const float* b2_o1  = (const float*)d_in[11];
    const float* w2_o2  = (const float*)d_in[12];
    const float* b2_o2  = (const float*)d_in[13];
    float* out = (float*)d_out;

    int N = in_sizes[0] / 128;
    int E = in_sizes[1] / 2;

    size_t smem_lin1 = (size_t)(128 * 65 + 64 * 129) * sizeof(float);
    size_t smem_mlp1 = (size_t)(64 * 65 * 2 + 64 * 40 + 64 * 65 * 2) * sizeof(float);
    cudaFuncSetAttribute(lin1_kernel, cudaFuncAttributeMaxDynamicSharedMemorySize, (int)smem_lin1);
    cudaFuncSetAttribute(mlp1_kernel, cudaFuncAttributeMaxDynamicSharedMemorySize, (int)smem_mlp1);

    int nodeBlocks = (N + 63) / 64;

    // CSR build (replaces atomic scatter)
    detect_idx_kernel<<<1, 32>>>(idx, E, (long long)N);
    zero_deg_kernel<<<(N + 255) / 256, 256>>>(N);
    csr_fill_kernel<<<(E + 255) / 256, 256>>>(idx, E);

    // layer 1
    lin1_kernel<<<nodeBlocks, 128, smem_lin1>>>(x, w1_lin, b1_lin, N);
    gather_kernel<64, 1><<<(N + 7) / 8, 256>>>(N);
    ovf_scatter_kernel<64, 1><<<64, 128>>>();
    mlp1_kernel<<<nodeBlocks, 128, smem_mlp1>>>(w1_o1, b1_o1, w1_o2, b1_o2,
                                                w2_lin, b2_lin, N);

    // layer 2
    gather_kernel<40, 2><<<(N + 7) / 8, 256>>>(N);
    ovf_scatter_kernel<40, 2><<<64, 128>>>();
    mlp2_kernel<<<nodeBlocks, 128>>>(w2_o1, b2_o1, w2_o2, b2_o2, out, N);
}

// round 6
// speedup vs baseline: 16.2630x; 1.4653x over previous
#include <cuda_runtime.h>
#include <cstdint>

#define NMAX 100000
#define EMAX 1000000
#define CAP 96
#define OVF_CAP 8192

// ---------------- scratch (no allocations allowed) ----------------
// NOTE: these symbols are ONLY referenced from device code. Passing a
// __device__ symbol as a kernel argument from host code binds the HOST shadow
// address (GB300 ATS makes it silently dereferenceable) — R2/R3/R4 bug.
__device__ float g_h1[NMAX * 64];    // lin1 output
__device__ float g_agg1[NMAX * 64];  // aggregation target layer 1
__device__ float g_t1[NMAX * 64];    // mid-MLP temp
__device__ float g_h2[NMAX * 40];    // lin2 output
__device__ float g_agg2[NMAX * 40];  // aggregation target layer 2
__device__ int   g_deg[NMAX];
__device__ int   g_col[(size_t)NMAX * CAP];
__device__ int   g_ovf_cnt;
__device__ int   g_ovf_src[OVF_CAP];
__device__ int   g_ovf_dst[OVF_CAP];
__device__ int   g_idx32;

__device__ __forceinline__ void red_add_f4(float* p, float4 v) {
    asm volatile("red.global.add.v4.f32 [%0], {%1,%2,%3,%4};"
                 :: "l"(p), "f"(v.x), "f"(v.y), "f"(v.z), "f"(v.w)
                 : "memory");
}

__device__ __forceinline__ uint32_t f2tf32(float x) {
    uint32_t r;
    asm("cvt.rna.tf32.f32 %0, %1;" : "=r"(r) : "f"(x));
    return r;
}

__device__ __forceinline__ void mma_tf32(float* d, const uint32_t* a, const uint32_t* b) {
    asm volatile(
        "mma.sync.aligned.m16n8k8.row.col.f32.tf32.tf32.f32 "
        "{%0,%1,%2,%3}, {%4,%5,%6,%7}, {%8,%9}, {%0,%1,%2,%3};"
        : "+f"(d[0]), "+f"(d[1]), "+f"(d[2]), "+f"(d[3])
        : "r"(a[0]), "r"(a[1]), "r"(a[2]), "r"(a[3]), "r"(b[0]), "r"(b[1]));
}

// ---------------- dtype probe: int64 vs int32 edge_index  [R5 verbatim] ----------------
__global__ void detect_idx_kernel(const long long* __restrict__ idx, int E, long long N) {
    if (blockIdx.x == 0 && threadIdx.x == 0) {
        int is32 = 0;
        int nc = E < 64 ? E : 64;
        for (int i = 0; i < nc; i++) {
            long long v = idx[i];
            if (v < 0 || v >= N) { is32 = 1; break; }
        }
        g_idx32 = is32;
    }
}

// ---------------- zero counters  [R5 verbatim] ----------------
__global__ void zero_deg_kernel(int N) {
    int i = blockIdx.x * blockDim.x + threadIdx.x;
    if (i < N) g_deg[i] = 0;
    if (i == 0) g_ovf_cnt = 0;
}

// ---------------- CSR bucket fill  [R5 verbatim] ----------------
__global__ void csr_fill_kernel(const long long* __restrict__ idx, int E) {
    int e = blockIdx.x * blockDim.x + threadIdx.x;
    if (e >= E) return;
    int s, d;
    if (g_idx32) {
        const int* p = (const int*)idx;
        s = p[e]; d = p[E + e];
    } else {
        s = (int)idx[e]; d = (int)idx[E + e];
    }
    int slot = atomicAdd(&g_deg[d], 1);
    if (slot < CAP) {
        g_col[(size_t)d * CAP + slot] = s;
    } else {
        int o = atomicAdd(&g_ovf_cnt, 1);
        if (o < OVF_CAP) { g_ovf_src[o] = s; g_ovf_dst[o] = d; }
    }
}

// ---------------- gather  [R5 verbatim] ----------------
template<int F, int LAYER>
__global__ void gather_kernel(int N) {
    const float* __restrict__ H   = (LAYER == 1) ? g_h1   : g_h2;
    float* __restrict__       AGG = (LAYER == 1) ? g_agg1 : g_agg2;
    int warp = (int)((blockIdx.x * (long long)blockDim.x + threadIdx.x) >> 5);
    int lane = threadIdx.x & 31;
    if (warp >= N) return;
    constexpr int L = F / 2;
    bool act = lane < L;
    float2 acc = make_float2(0.f, 0.f);
    if (act) acc = *(const float2*)&H[(size_t)warp * F + lane * 2];
    int deg = g_deg[warp];
    if (deg > CAP) deg = CAP;
    const int* cp = g_col + (size_t)warp * CAP;
    int j = 0;
    for (; j + 4 <= deg; j += 4) {
        int4 s = *(const int4*)&cp[j];
        float2 v0 = make_float2(0.f,0.f), v1 = v0, v2 = v0, v3 = v0;
        if (act) {
            v0 = *(const float2*)&H[(size_t)s.x * F + lane * 2];
            v1 = *(const float2*)&H[(size_t)s.y * F + lane * 2];
            v2 = *(const float2*)&H[(size_t)s.z * F + lane * 2];
            v3 = *(const float2*)&H[(size_t)s.w * F + lane * 2];
        }
        acc.x += (v0.x + v1.x) + (v2.x + v3.x);
        acc.y += (v0.y + v1.y) + (v2.y + v3.y);
    }
    for (; j < deg; j++) {
        int s = cp[j];
        if (act) {
            float2 v = *(const float2*)&H[(size_t)s * F + lane * 2];
            acc.x += v.x; acc.y += v.y;
        }
    }
    if (act) *(float2*)&AGG[(size_t)warp * F + lane * 2] = acc;
}

// ---------------- overflow scatter  [R5 verbatim] ----------------
template<int F, int LAYER>
__global__ void ovf_scatter_kernel() {
    const float* __restrict__ H   = (LAYER == 1) ? g_h1   : g_h2;
    float* __restrict__       AGG = (LAYER == 1) ? g_agg1 : g_agg2;
    int cnt = g_ovf_cnt;
    if (cnt > OVF_CAP) cnt = OVF_CAP;
    int total = cnt * (F / 4);
    for (int i = blockIdx.x * blockDim.x + threadIdx.x; i < total;
         i += gridDim.x * blockDim.x) {
        int e = i / (F / 4);
        int q = (i - e * (F / 4)) * 4;
        int s = g_ovf_src[e], d = g_ovf_dst[e];
        float4 v = *(const float4*)&H[(size_t)s * F + q];
        red_add_f4(&AGG[(size_t)d * F + q], v);
    }
}

// ---------------- tf32 MMA GEMM: Y = [relu]( relu?(X) @ W^T + b ) ----------------
// Block: 256 threads (8 warps), 128-node tile; warp owns 16 nodes x NF feats.
// A/B staged in smem in fragment-ready layouts:
//   sA[kt][warp][lane][4]  (tf32 bits)    sB[kt][nt][lane][2]
// Buffer selection is DEVICE-side via XS/YS (0 = use pointer argument).
//   XS: 0=Xa  2=g_agg1  3=g_t1  5=g_agg2
//   YS: 0=Ya  1=g_h1    3=g_t1  4=g_h2  5=g_agg2
// In-place (XS==YS buffer) is safe: each block reads only its own 128 rows
// into smem (single K chunk for KIN<=64) before writing them.
template<int KIN, int NF, bool RIN, bool ROUT, int XS, int YS>
__global__ void __launch_bounds__(256)
mma_gemm(const float* __restrict__ Xa, const float* __restrict__ W,
         const float* __restrict__ bias, float* __restrict__ Ya, int N)
{
    constexpr int KT  = KIN / 8;                  // total k-tiles
    constexpr int KC  = (KIN > 64) ? 64 : KIN;    // k elems per chunk
    constexpr int KTC = KC / 8;                   // k-tiles per chunk
    constexpr int NCH = KIN / KC;                 // chunks
    constexpr int NT  = NF / 8;                   // n-tiles

    const float* X = (XS == 0) ? Xa :
                     (XS == 2) ? (const float*)g_agg1 :
                     (XS == 3) ? (const float*)g_t1 : (const float*)g_agg2;
    float* Y = (YS == 0) ? Ya :
               (YS == 1) ? (float*)g_h1 :
               (YS == 3) ? (float*)g_t1 :
               (YS == 4) ? (float*)g_h2 : (float*)g_agg2;

    extern __shared__ float sm[];
    uint32_t* sA = (uint32_t*)sm;                 // KTC*8*32*4
    uint32_t* sB = (uint32_t*)(sm + KTC * 1024);  // KT*NT*32*2

    int t = threadIdx.x;
    int warp = t >> 5, lane = t & 31;
    int n0 = blockIdx.x * 128;

    // stage B fragments (full K, once)
    for (int i = t; i < KT * NT * 32; i += 256) {
        int l = i & 31;
        int tile = i >> 5;
        int nt = tile % NT, kt = tile / NT;
        int f  = nt * 8 + (l >> 2);
        int k0 = kt * 8 + (l & 3);
        sB[i * 2 + 0] = f2tf32(W[f * KIN + k0]);
        sB[i * 2 + 1] = f2tf32(W[f * KIN + k0 + 4]);
    }

    float acc[NT][4];
#pragma unroll
    for (int nt = 0; nt < NT; nt++)
#pragma unroll
        for (int j = 0; j < 4; j++) acc[nt][j] = 0.f;

    for (int ch = 0; ch < NCH; ch++) {
        if (ch) __syncthreads();
        // stage A chunk into fragment layout (coalesced global read)
        for (int i = t; i < 128 * KC; i += 256) {
            int n = i / KC, k = i - n * KC;
            int gn = n0 + n;
            float v = (gn < N) ? X[(size_t)gn * KIN + ch * KC + k] : 0.f;
            if (RIN) v = fmaxf(v, 0.f);
            int wg = n >> 4, r = n & 15, kt = k >> 3, ki = k & 7;
            int l   = ((r & 7) << 2) | (ki & 3);
            int reg = ((ki >> 2) << 1) | (r >> 3);
            sA[((kt * 8 + wg) * 32 + l) * 4 + reg] = f2tf32(v);
        }
        __syncthreads();

#pragma unroll
        for (int kt = 0; kt < KTC; kt++) {
            uint32_t a[4];
            *(float4*)a = *(const float4*)&sA[((kt * 8 + warp) * 32 + lane) * 4];
#pragma unroll
            for (int nt = 0; nt < NT; nt++) {
                uint32_t b[2];
                *(float2*)b = *(const float2*)&sB[(((ch * KTC + kt) * NT + nt) * 32 + lane) * 2];
                mma_tf32(acc[nt], a, b);
            }
        }
    }

    // epilogue: C frag -> global (+bias, optional relu)
    int row = lane >> 2;
    int cb  = (lane & 3) * 2;
    int gn1 = n0 + warp * 16 + row;
    int gn2 = gn1 + 8;
#pragma unroll
    for (int nt = 0; nt < NT; nt++) {
        int f = nt * 8 + cb;
        float bx = __ldg(bias + f), by = __ldg(bias + f + 1);
        float2 v1 = make_float2(acc[nt][0] + bx, acc[nt][1] + by);
        float2 v2 = make_float2(acc[nt][2] + bx, acc[nt][3] + by);
        if (ROUT) {
            v1.x = fmaxf(v1.x, 0.f); v1.y = fmaxf(v1.y, 0.f);
            v2.x = fmaxf(v2.x, 0.f); v2.y = fmaxf(v2.y, 0.f);
        }
        if (gn1 < N) *(float2*)&Y[(size_t)gn1 * NF + f] = v1;
        if (gn2 < N) *(float2*)&Y[(size_t)gn2 * NF + f] = v2;
    }
}

// ---------------- launch ----------------
extern "C" void kernel_launch(void* const* d_in, const int* in_sizes, int n_in,
                              void* d_out, int out_size) {
    const float*     x   = (const float*)d_in[0];
    const long long* idx = (const long long*)d_in[1];
    const float* w1_lin = (const float*)d_in[2];
    const float* b1_lin = (const float*)d_in[3];
    const float* w1_o1  = (const float*)d_in[4];
    const float* b1_o1  = (const float*)d_in[5];
    const float* w1_o2  = (const float*)d_in[6];
    const float* b1_o2  = (const float*)d_in[7];
    const float* w2_lin = (const float*)d_in[8];
    const float* b2_lin = (const float*)d_in[9];
    const float* w2_o1  = (const float*)d_in[10];
    const float* b2_o1  = (const float*)d_in[11];
    const float* w2_o2  = (const float*)d_in[12];
    const float* b2_o2  = (const float*)d_in[13];
    float* out = (float*)d_out;

    int N = in_sizes[0] / 128;
    int E = in_sizes[1] / 2;

    // dynamic smem bytes: (KTC*1024 + KT*NT*64) * 4
    const int SM_128_64 = (8 * 1024 + 16 * 8 * 64) * 4;   // 65536
    const int SM_64_64  = (8 * 1024 +  8 * 8 * 64) * 4;   // 49152
    const int SM_64_40  = (8 * 1024 +  8 * 5 * 64) * 4;   // 43008
    const int SM_40_40  = (5 * 1024 +  5 * 5 * 64) * 4;   // 26880

    cudaFuncSetAttribute((const void*)mma_gemm<128,64,false,false,0,1>,
                         cudaFuncAttributeMaxDynamicSharedMemorySize, SM_128_64);
    cudaFuncSetAttribute((const void*)mma_gemm<64,64,true,true,2,3>,
                         cudaFuncAttributeMaxDynamicSharedMemorySize, SM_64_64);
    cudaFuncSetAttribute((const void*)mma_gemm<64,64,false,true,3,3>,
                         cudaFuncAttributeMaxDynamicSharedMemorySize, SM_64_64);
    cudaFuncSetAttribute((const void*)mma_gemm<64,40,false,false,3,4>,
                         cudaFuncAttributeMaxDynamicSharedMemorySize, SM_64_40);
    cudaFuncSetAttribute((const void*)mma_gemm<40,40,true,true,5,5>,
                         cudaFuncAttributeMaxDynamicSharedMemorySize, SM_40_40);
    cudaFuncSetAttribute((const void*)mma_gemm<40,40,false,false,5,0>,
                         cudaFuncAttributeMaxDynamicSharedMemorySize, SM_40_40);

    int gemmBlocks = (N + 127) / 128;

    // CSR build
    detect_idx_kernel<<<1, 32>>>(idx, E, (long long)N);
    zero_deg_kernel<<<(N + 255) / 256, 256>>>(N);
    csr_fill_kernel<<<(E + 255) / 256, 256>>>(idx, E);

    // layer 1: lin1 -> gather -> o1(relu-in, relu-out) -> o2(relu-out = inter-conv relu)
    mma_gemm<128,64,false,false,0,1><<<gemmBlocks, 256, SM_128_64>>>(x, w1_lin, b1_lin, nullptr, N);
    gather_kernel<64, 1><<<(N + 7) / 8, 256>>>(N);
    ovf_scatter_kernel<64, 1><<<64, 128>>>();
    mma_gemm<64,64,true,true,2,3><<<gemmBlocks, 256, SM_64_64>>>(nullptr, w1_o1, b1_o1, nullptr, N);
    mma_gemm<64,64,false,true,3,3><<<gemmBlocks, 256, SM_64_64>>>(nullptr, w1_o2, b1_o2, nullptr, N);

    // layer 2: lin2 -> gather -> o1 -> o2 -> out
    mma_gemm<64,40,false,false,3,4><<<gemmBlocks, 256, SM_64_40>>>(nullptr, w2_lin, b2_lin, nullptr, N);
    gather_kernel<40, 2><<<(N + 7) / 8, 256>>>(N);
    ovf_scatter_kernel<40, 2><<<64, 128>>>();
    mma_gemm<40,40,true,true,5,5><<<gemmBlocks, 256, SM_40_40>>>(nullptr, w2_o1, b2_o1, nullptr, N);
    mma_gemm<40,40,false,false,5,0><<<gemmBlocks, 256, SM_40_40>>>(nullptr, w2_o2, b2_o2, out, N);
}

// round 7
// speedup vs baseline: 16.3584x; 1.0059x over previous
#include <cuda_runtime.h>
#include <cstdint>

#define NMAX 100000
#define EMAX 1000000
#define CAP 96
#define OVF_CAP 8192

// ---------------- scratch (no allocations allowed) ----------------
// NOTE: symbols ONLY referenced from device code (ATS host-shadow bug).
__device__ float g_h1[NMAX * 64];    // lin1 output
__device__ float g_agg1[NMAX * 64];  // layer-1 aggregation
__device__ float g_h2[NMAX * 40];    // fused mid-MLP output
__device__ float g_agg2[NMAX * 40];  // layer-2 aggregation
__device__ int   g_deg[NMAX];
__device__ int   g_col[(size_t)NMAX * CAP];
__device__ int   g_ovf_cnt;
__device__ int   g_ovf_src[OVF_CAP];
__device__ int   g_ovf_dst[OVF_CAP];
__device__ int   g_idx32;

__device__ __forceinline__ void red_add_f4(float* p, float4 v) {
    asm volatile("red.global.add.v4.f32 [%0], {%1,%2,%3,%4};"
                 :: "l"(p), "f"(v.x), "f"(v.y), "f"(v.z), "f"(v.w)
                 : "memory");
}

__device__ __forceinline__ uint32_t f2tf32(float x) {
    uint32_t r;
    asm("cvt.rna.tf32.f32 %0, %1;" : "=r"(r) : "f"(x));
    return r;
}

__device__ __forceinline__ void mma_tf32(float* d, const uint32_t* a, const uint32_t* b) {
    asm volatile(
        "mma.sync.aligned.m16n8k8.row.col.f32.tf32.tf32.f32 "
        "{%0,%1,%2,%3}, {%4,%5,%6,%7}, {%8,%9}, {%0,%1,%2,%3};"
        : "+f"(d[0]), "+f"(d[1]), "+f"(d[2]), "+f"(d[3])
        : "r"(a[0]), "r"(a[1]), "r"(a[2]), "r"(a[3]), "r"(b[0]), "r"(b[1]));
}

// ---------------- dtype probe ----------------
__global__ void detect_idx_kernel(const long long* __restrict__ idx, int E, long long N) {
    if (blockIdx.x == 0 && threadIdx.x == 0) {
        int is32 = 0;
        int nc = E < 64 ? E : 64;
        for (int i = 0; i < nc; i++) {
            long long v = idx[i];
            if (v < 0 || v >= N) { is32 = 1; break; }
        }
        g_idx32 = is32;
    }
}

__global__ void zero_deg_kernel(int N) {
    int i = blockIdx.x * blockDim.x + threadIdx.x;
    if (i < N) g_deg[i] = 0;
    if (i == 0) g_ovf_cnt = 0;
}

__global__ void csr_fill_kernel(const long long* __restrict__ idx, int E) {
    int e = blockIdx.x * blockDim.x + threadIdx.x;
    if (e >= E) return;
    int s, d;
    if (g_idx32) {
        const int* p = (const int*)idx;
        s = p[e]; d = p[E + e];
    } else {
        s = (int)idx[e]; d = (int)idx[E + e];
    }
    int slot = atomicAdd(&g_deg[d], 1);
    if (slot < CAP) {
        g_col[(size_t)d * CAP + slot] = s;
    } else {
        int o = atomicAdd(&g_ovf_cnt, 1);
        if (o < OVF_CAP) { g_ovf_src[o] = s; g_ovf_dst[o] = d; }
    }
}

// ---------------- gather  [R5 verbatim] ----------------
template<int F, int LAYER>
__global__ void gather_kernel(int N) {
    const float* __restrict__ H   = (LAYER == 1) ? g_h1   : g_h2;
    float* __restrict__       AGG = (LAYER == 1) ? g_agg1 : g_agg2;
    int warp = (int)((blockIdx.x * (long long)blockDim.x + threadIdx.x) >> 5);
    int lane = threadIdx.x & 31;
    if (warp >= N) return;
    constexpr int L = F / 2;
    bool act = lane < L;
    float2 acc = make_float2(0.f, 0.f);
    if (act) acc = *(const float2*)&H[(size_t)warp * F + lane * 2];
    int deg = g_deg[warp];
    if (deg > CAP) deg = CAP;
    const int* cp = g_col + (size_t)warp * CAP;
    int j = 0;
    for (; j + 4 <= deg; j += 4) {
        int4 s = *(const int4*)&cp[j];
        float2 v0 = make_float2(0.f,0.f), v1 = v0, v2 = v0, v3 = v0;
        if (act) {
            v0 = *(const float2*)&H[(size_t)s.x * F + lane * 2];
            v1 = *(const float2*)&H[(size_t)s.y * F + lane * 2];
            v2 = *(const float2*)&H[(size_t)s.z * F + lane * 2];
            v3 = *(const float2*)&H[(size_t)s.w * F + lane * 2];
        }
        acc.x += (v0.x + v1.x) + (v2.x + v3.x);
        acc.y += (v0.y + v1.y) + (v2.y + v3.y);
    }
    for (; j < deg; j++) {
        int s = cp[j];
        if (act) {
            float2 v = *(const float2*)&H[(size_t)s * F + lane * 2];
            acc.x += v.x; acc.y += v.y;
        }
    }
    if (act) *(float2*)&AGG[(size_t)warp * F + lane * 2] = acc;
}

template<int F, int LAYER>
__global__ void ovf_scatter_kernel() {
    const float* __restrict__ H   = (LAYER == 1) ? g_h1   : g_h2;
    float* __restrict__       AGG = (LAYER == 1) ? g_agg1 : g_agg2;
    int cnt = g_ovf_cnt;
    if (cnt > OVF_CAP) cnt = OVF_CAP;
    int total = cnt * (F / 4);
    for (int i = blockIdx.x * blockDim.x + threadIdx.x; i < total;
         i += gridDim.x * blockDim.x) {
        int e = i / (F / 4);
        int q = (i - e * (F / 4)) * 4;
        int s = g_ovf_src[e], d = g_ovf_dst[e];
        float4 v = *(const float4*)&H[(size_t)s * F + q];
        red_add_f4(&AGG[(size_t)d * F + q], v);
    }
}

// ======== shared device helpers for tf32 fragment GEMM ========
// A-fragment smem layout (reg-major): sF[(tile*4 + reg)*32 + lane]
//   tile = kt*8 + warp_row_group. Staging writes uint4 (4 lanes, same reg).
// B-fragment layout: sB[((kt*NT + nt)*32 + lane)*2 + {0,1}]

// Stage weight W[NF][K] (row-major) into B fragments. THREADS=256.
template<int K, int NT>
__device__ __forceinline__ void stage_B(const float* __restrict__ W, uint32_t* sB, int t) {
    constexpr int KT = K / 8;
    for (int i = t; i < KT * NT * 32; i += 256) {
        int l = i & 31;
        int tile = i >> 5;
        int nt = tile % NT, kt = tile / NT;
        int f  = nt * 8 + (l >> 2);
        int k0 = kt * 8 + (l & 3);
        sB[i * 2 + 0] = f2tf32(W[f * K + k0]);
        sB[i * 2 + 1] = f2tf32(W[f * K + k0 + 4]);
    }
}

// Restage activations sAct[128][PAD] (first K cols) into A fragments.
template<int K, int PAD>
__device__ __forceinline__ void restage_A(const float* sAct, uint32_t* sF, int t) {
    constexpr int Q = K / 4;            // float4s per row
    for (int i = t; i < 128 * Q; i += 256) {
        int n = i / Q, q = i - n * Q, k = q * 4;
        int wg = n >> 4, r = n & 15, kt = k >> 3, ki = k & 7;
        int reg = ((ki >> 2) << 1) | (r >> 3);
        int l0  = (r & 7) << 2;
        float4 v = *(const float4*)&sAct[n * PAD + k];
        uint4 u = make_uint4(f2tf32(v.x), f2tf32(v.y), f2tf32(v.z), f2tf32(v.w));
        *(uint4*)&sF[((kt * 8 + wg) * 4 + reg) * 32 + l0] = u;
    }
}

// One MMA stage over staged fragments; result in acc[NT][4].
template<int K, int NT>
__device__ __forceinline__ void mma_stage(const uint32_t* sF, const uint32_t* sB,
                                          float acc[][4], int warp, int lane) {
    constexpr int KT = K / 8;
#pragma unroll
    for (int nt = 0; nt < NT; nt++)
#pragma unroll
        for (int j = 0; j < 4; j++) acc[nt][j] = 0.f;
#pragma unroll
    for (int kt = 0; kt < KT; kt++) {
        uint32_t a[4];
#pragma unroll
        for (int reg = 0; reg < 4; reg++)
            a[reg] = sF[((kt * 8 + warp) * 4 + reg) * 32 + lane];
#pragma unroll
        for (int nt = 0; nt < NT; nt++) {
            uint32_t b[2];
            *(float2*)b = *(const float2*)&sB[((kt * NT + nt) * 32 + lane) * 2];
            mma_tf32(acc[nt], a, b);
        }
    }
}

// Epilogue: C frags -> sAct[128][PAD] with bias (+relu).
template<int NT, int PAD, bool RELU>
__device__ __forceinline__ void epi_to_smem(float acc[][4], const float* __restrict__ bias,
                                            float* sAct, int warp, int lane) {
    int row = lane >> 2;
    int cb  = (lane & 3) * 2;
    int r1 = warp * 16 + row, r2 = r1 + 8;
#pragma unroll
    for (int nt = 0; nt < NT; nt++) {
        int f = nt * 8 + cb;
        float bx = __ldg(bias + f), by = __ldg(bias + f + 1);
        float2 v1 = make_float2(acc[nt][0] + bx, acc[nt][1] + by);
        float2 v2 = make_float2(acc[nt][2] + bx, acc[nt][3] + by);
        if (RELU) {
            v1.x = fmaxf(v1.x, 0.f); v1.y = fmaxf(v1.y, 0.f);
            v2.x = fmaxf(v2.x, 0.f); v2.y = fmaxf(v2.y, 0.f);
        }
        *(float2*)&sAct[r1 * PAD + f] = v1;
        *(float2*)&sAct[r2 * PAD + f] = v2;
    }
}

// Epilogue: C frags -> global Y[N][NF] with bias (+relu).
template<int NT, int NF, bool RELU>
__device__ __forceinline__ void epi_to_gmem(float acc[][4], const float* __restrict__ bias,
                                            float* __restrict__ Y, int n0, int N,
                                            int warp, int lane) {
    int row = lane >> 2;
    int cb  = (lane & 3) * 2;
    int gn1 = n0 + warp * 16 + row;
    int gn2 = gn1 + 8;
#pragma unroll
    for (int nt = 0; nt < NT; nt++) {
        int f = nt * 8 + cb;
        float bx = __ldg(bias + f), by = __ldg(bias + f + 1);
        float2 v1 = make_float2(acc[nt][0] + bx, acc[nt][1] + by);
        float2 v2 = make_float2(acc[nt][2] + bx, acc[nt][3] + by);
        if (RELU) {
            v1.x = fmaxf(v1.x, 0.f); v1.y = fmaxf(v1.y, 0.f);
            v2.x = fmaxf(v2.x, 0.f); v2.y = fmaxf(v2.y, 0.f);
        }
        if (gn1 < N) *(float2*)&Y[(size_t)gn1 * NF + f] = v1;
        if (gn2 < N) *(float2*)&Y[(size_t)gn2 * NF + f] = v2;
    }
}

// ---------------- lin1: g_h1 = x @ W^T + b  (128 -> 64) ----------------
// 256 threads, 128-node tile, two 64-wide K chunks accumulated.
__global__ void __launch_bounds__(256)
lin1_mma(const float* __restrict__ X, const float* __restrict__ W,
         const float* __restrict__ bias, int N)
{
    constexpr int NT = 8;
    extern __shared__ float sm[];
    uint32_t* sF = (uint32_t*)sm;            // 8 ktiles * 8 wg * 4 reg * 32 = 8192
    uint32_t* sB = sF + 8192;                // 16 kt * 8 nt * 64 = 8192

    int t = threadIdx.x, warp = t >> 5, lane = t & 31;
    int n0 = blockIdx.x * 128;

    stage_B<128, NT>(W, sB, t);

    float acc[NT][4];
#pragma unroll
    for (int nt = 0; nt < NT; nt++)
#pragma unroll
        for (int j = 0; j < 4; j++) acc[nt][j] = 0.f;

    for (int ch = 0; ch < 2; ch++) {
        if (ch) __syncthreads();
        // stage A chunk straight from global (float4), fragment layout
        for (int i = t; i < 128 * 16; i += 256) {
            int n = i >> 4, q = i & 15, k = q * 4;
            int gn = n0 + n;
            float4 v = (gn < N) ? *(const float4*)&X[(size_t)gn * 128 + ch * 64 + k]
                                : make_float4(0.f, 0.f, 0.f, 0.f);
            int wg = n >> 4, r = n & 15, kt = k >> 3, ki = k & 7;
            int reg = ((ki >> 2) << 1) | (r >> 3);
            int l0  = (r & 7) << 2;
            uint4 u = make_uint4(f2tf32(v.x), f2tf32(v.y), f2tf32(v.z), f2tf32(v.w));
            *(uint4*)&sF[((kt * 8 + wg) * 4 + reg) * 32 + l0] = u;
        }
        __syncthreads();
#pragma unroll
        for (int kt = 0; kt < 8; kt++) {
            uint32_t a[4];
#pragma unroll
            for (int reg = 0; reg < 4; reg++)
                a[reg] = sF[((kt * 8 + warp) * 4 + reg) * 32 + lane];
#pragma unroll
            for (int nt = 0; nt < NT; nt++) {
                uint32_t b[2];
                *(float2*)b = *(const float2*)&sB[(((ch * 8 + kt) * NT + nt) * 32 + lane) * 2];
                mma_tf32(acc[nt], a, b);
            }
        }
    }
    epi_to_gmem<NT, 64, false>(acc, bias, g_h1, n0, N, warp, lane);
}

// ---------------- fused mid-MLP ----------------
// a=relu(agg1); b=relu(a@W1^T+b1); c=relu(b@W2^T+b2); h2 = c@W3^T+b3 (64->40)
__global__ void __launch_bounds__(256)
fused_mlp1(const float* __restrict__ W1, const float* __restrict__ b1,
           const float* __restrict__ W2, const float* __restrict__ b2,
           const float* __restrict__ W3, const float* __restrict__ b3, int N)
{
    constexpr int PAD = 68;
    extern __shared__ float sm[];
    float* sAct   = sm;                          // 128*68 floats
    uint32_t* sF  = (uint32_t*)(sm + 128 * PAD); // 8192 u32
    uint32_t* sB1 = sF + 8192;                   // 4096 u32
    uint32_t* sB2 = sB1 + 4096;                  // 4096 u32
    uint32_t* sB3 = sB2 + 4096;                  // 2560 u32

    int t = threadIdx.x, warp = t >> 5, lane = t & 31;
    int n0 = blockIdx.x * 128;

    stage_B<64, 8>(W1, sB1, t);
    stage_B<64, 8>(W2, sB2, t);
    stage_B<64, 5>(W3, sB3, t);

    // load relu(agg1) into sAct
    for (int i = t; i < 128 * 16; i += 256) {
        int n = i >> 4, q = i & 15;
        int gn = n0 + n;
        float4 v = (gn < N) ? *(const float4*)&g_agg1[(size_t)gn * 64 + q * 4]
                            : make_float4(0.f, 0.f, 0.f, 0.f);
        v.x = fmaxf(v.x, 0.f); v.y = fmaxf(v.y, 0.f);
        v.z = fmaxf(v.z, 0.f); v.w = fmaxf(v.w, 0.f);
        *(float4*)&sAct[n * PAD + q * 4] = v;
    }
    __syncthreads();

    float acc[8][4];

    // stage 1: relu(a@W1^T+b1) -> sAct
    restage_A<64, PAD>(sAct, sF, t);
    __syncthreads();
    mma_stage<64, 8>(sF, sB1, acc, warp, lane);
    __syncthreads();   // all frag reads done before sAct overwrite
    epi_to_smem<8, PAD, true>(acc, b1, sAct, warp, lane);
    __syncthreads();

    // stage 2: relu(b@W2^T+b2) -> sAct
    restage_A<64, PAD>(sAct, sF, t);
    __syncthreads();
    mma_stage<64, 8>(sF, sB2, acc, warp, lane);
    __syncthreads();
    epi_to_smem<8, PAD, true>(acc, b2, sAct, warp, lane);
    __syncthreads();

    // stage 3: c@W3^T+b3 -> g_h2 (64 -> 40)
    restage_A<64, PAD>(sAct, sF, t);
    __syncthreads();
    mma_stage<64, 5>(sF, sB3, acc, warp, lane);
    epi_to_gmem<5, 40, false>(acc, b3, g_h2, n0, N, warp, lane);
}

// ---------------- fused final MLP ----------------
// a=relu(agg2); b=relu(a@W1^T+b1); out = b@W2^T+b2  (40->40->40)
__global__ void __launch_bounds__(256)
fused_mlp2(const float* __restrict__ W1, const float* __restrict__ b1,
           const float* __restrict__ W2, const float* __restrict__ b2,
           float* __restrict__ out, int N)
{
    constexpr int PAD = 44;
    extern __shared__ float sm[];
    float* sAct   = sm;                          // 128*44 floats
    uint32_t* sF  = (uint32_t*)(sm + 128 * PAD); // 5*8*4*32 = 5120 u32
    uint32_t* sB1 = sF + 5120;                   // 5*5*64 = 1600 u32
    uint32_t* sB2 = sB1 + 1600;                  // 1600 u32

    int t = threadIdx.x, warp = t >> 5, lane = t & 31;
    int n0 = blockIdx.x * 128;

    stage_B<40, 5>(W1, sB1, t);
    stage_B<40, 5>(W2, sB2, t);

    for (int i = t; i < 128 * 10; i += 256) {
        int n = i / 10, q = i - n * 10;
        int gn = n0 + n;
        float4 v = (gn < N) ? *(const float4*)&g_agg2[(size_t)gn * 40 + q * 4]
                            : make_float4(0.f, 0.f, 0.f, 0.f);
        v.x = fmaxf(v.x, 0.f); v.y = fmaxf(v.y, 0.f);
        v.z = fmaxf(v.z, 0.f); v.w = fmaxf(v.w, 0.f);
        *(float4*)&sAct[n * PAD + q * 4] = v;
    }
    __syncthreads();

    float acc[5][4];

    restage_A<40, PAD>(sAct, sF, t);
    __syncthreads();
    mma_stage<40, 5>(sF, sB1, acc, warp, lane);
    __syncthreads();
    epi_to_smem<5, PAD, true>(acc, b1, sAct, warp, lane);
    __syncthreads();

    restage_A<40, PAD>(sAct, sF, t);
    __syncthreads();
    mma_stage<40, 5>(sF, sB2, acc, warp, lane);
    epi_to_gmem<5, 40, false>(acc, b2, out, n0, N, warp, lane);
}

// ---------------- launch ----------------
extern "C" void kernel_launch(void* const* d_in, const int* in_sizes, int n_in,
                              void* d_out, int out_size) {
    const float*     x   = (const float*)d_in[0];
    const long long* idx = (const long long*)d_in[1];
    const float* w1_lin = (const float*)d_in[2];
    const float* b1_lin = (const float*)d_in[3];
    const float* w1_o1  = (const float*)d_in[4];
    const float* b1_o1  = (const float*)d_in[5];
    const float* w1_o2  = (const float*)d_in[6];
    const float* b1_o2  = (const float*)d_in[7];
    const float* w2_lin = (const float*)d_in[8];
    const float* b2_lin = (const float*)d_in[9];
    const float* w2_o1  = (const float*)d_in[10];
    const float* b2_o1  = (const float*)d_in[11];
    const float* w2_o2  = (const float*)d_in[12];
    const float* b2_o2  = (const float*)d_in[13];
    float* out = (float*)d_out;

    int N = in_sizes[0] / 128;
    int E = in_sizes[1] / 2;

    const int SM_LIN1 = (8192 + 8192) * 4;                           // 65536
    const int SM_MLP1 = (128 * 68 + 8192 + 4096 + 4096 + 2560) * 4;  // 110592
    const int SM_MLP2 = (128 * 44 + 5120 + 1600 + 1600) * 4;         // 55808

    cudaFuncSetAttribute(lin1_mma,   cudaFuncAttributeMaxDynamicSharedMemorySize, SM_LIN1);
    cudaFuncSetAttribute(fused_mlp1, cudaFuncAttributeMaxDynamicSharedMemorySize, SM_MLP1);
    cudaFuncSetAttribute(fused_mlp2, cudaFuncAttributeMaxDynamicSharedMemorySize, SM_MLP2);

    int gemmBlocks = (N + 127) / 128;

    // CSR build
    detect_idx_kernel<<<1, 32>>>(idx, E, (long long)N);
    zero_deg_kernel<<<(N + 255) / 256, 256>>>(N);
    csr_fill_kernel<<<(E + 255) / 256, 256>>>(idx, E);

    // layer 1
    lin1_mma<<<gemmBlocks, 256, SM_LIN1>>>(x, w1_lin, b1_lin, N);
    gather_kernel<64, 1><<<(N + 7) / 8, 256>>>(N);
    ovf_scatter_kernel<64, 1><<<64, 128>>>();
    fused_mlp1<<<gemmBlocks, 256, SM_MLP1>>>(w1_o1, b1_o1, w1_o2, b1_o2,
                                             w2_lin, b2_lin, N);

    // layer 2
    gather_kernel<40, 2><<<(N + 7) / 8, 256>>>(N);
    ovf_scatter_kernel<40, 2><<<64, 128>>>();
    fused_mlp2<<<gemmBlocks, 256, SM_MLP2>>>(w2_o1, b2_o1, w2_o2, b2_o2, out, N);
}

// round 8
// speedup vs baseline: 17.1449x; 1.0481x over previous
#include <cuda_runtime.h>
#include <cstdint>

#define NMAX 100000
#define EMAX 1000000
#define CAP 96
#define OVF_CAP 8192

// ---------------- scratch (no allocations allowed) ----------------
// NOTE: symbols ONLY referenced from device code, except via
// cudaGetSymbolAddress (true device address) for memset nodes.
__device__ float g_h1[NMAX * 64];    // lin1 output
__device__ float g_agg1[NMAX * 64];  // layer-1 aggregation
__device__ float g_h2[NMAX * 40];    // fused mid-MLP output
__device__ float g_agg2[NMAX * 40];  // layer-2 aggregation
__device__ int   g_deg[NMAX];
__device__ int   g_col[(size_t)NMAX * CAP];
__device__ int   g_ovf_cnt;
__device__ int   g_ovf_src[OVF_CAP];
__device__ int   g_ovf_dst[OVF_CAP];
__device__ int   g_idx32;

__device__ __forceinline__ void red_add_f4(float* p, float4 v) {
    asm volatile("red.global.add.v4.f32 [%0], {%1,%2,%3,%4};"
                 :: "l"(p), "f"(v.x), "f"(v.y), "f"(v.z), "f"(v.w)
                 : "memory");
}

__device__ __forceinline__ uint32_t f2tf32(float x) {
    uint32_t r;
    asm("cvt.rna.tf32.f32 %0, %1;" : "=r"(r) : "f"(x));
    return r;
}

__device__ __forceinline__ void mma_tf32(float* d, const uint32_t* a, const uint32_t* b) {
    asm volatile(
        "mma.sync.aligned.m16n8k8.row.col.f32.tf32.tf32.f32 "
        "{%0,%1,%2,%3}, {%4,%5,%6,%7}, {%8,%9}, {%0,%1,%2,%3};"
        : "+f"(d[0]), "+f"(d[1]), "+f"(d[2]), "+f"(d[3])
        : "r"(a[0]), "r"(a[1]), "r"(a[2]), "r"(a[3]), "r"(b[0]), "r"(b[1]));
}

// ---------------- dtype probe ----------------
__global__ void detect_idx_kernel(const long long* __restrict__ idx, int E, long long N) {
    if (blockIdx.x == 0 && threadIdx.x == 0) {
        int is32 = 0;
        int nc = E < 64 ? E : 64;
        for (int i = 0; i < nc; i++) {
            long long v = idx[i];
            if (v < 0 || v >= N) { is32 = 1; break; }
        }
        g_idx32 = is32;
    }
}

__global__ void csr_fill_kernel(const long long* __restrict__ idx, int E) {
    int e = blockIdx.x * blockDim.x + threadIdx.x;
    if (e >= E) return;
    int s, d;
    if (g_idx32) {
        const int* p = (const int*)idx;
        s = p[e]; d = p[E + e];
    } else {
        s = (int)idx[e]; d = (int)idx[E + e];
    }
    int slot = atomicAdd(&g_deg[d], 1);
    if (slot < CAP) {
        g_col[(size_t)d * CAP + slot] = s;
    } else {
        int o = atomicAdd(&g_ovf_cnt, 1);
        if (o < OVF_CAP) { g_ovf_src[o] = s; g_ovf_dst[o] = d; }
    }
}

// ---------------- gather  [R5 verbatim] ----------------
template<int F, int LAYER>
__global__ void gather_kernel(int N) {
    const float* __restrict__ H   = (LAYER == 1) ? g_h1   : g_h2;
    float* __restrict__       AGG = (LAYER == 1) ? g_agg1 : g_agg2;
    int warp = (int)((blockIdx.x * (long long)blockDim.x + threadIdx.x) >> 5);
    int lane = threadIdx.x & 31;
    if (warp >= N) return;
    constexpr int L = F / 2;
    bool act = lane < L;
    float2 acc = make_float2(0.f, 0.f);
    if (act) acc = *(const float2*)&H[(size_t)warp * F + lane * 2];
    int deg = g_deg[warp];
    if (deg > CAP) deg = CAP;
    const int* cp = g_col + (size_t)warp * CAP;
    int j = 0;
    for (; j + 4 <= deg; j += 4) {
        int4 s = *(const int4*)&cp[j];
        float2 v0 = make_float2(0.f,0.f), v1 = v0, v2 = v0, v3 = v0;
        if (act) {
            v0 = *(const float2*)&H[(size_t)s.x * F + lane * 2];
            v1 = *(const float2*)&H[(size_t)s.y * F + lane * 2];
            v2 = *(const float2*)&H[(size_t)s.z * F + lane * 2];
            v3 = *(const float2*)&H[(size_t)s.w * F + lane * 2];
        }
        acc.x += (v0.x + v1.x) + (v2.x + v3.x);
        acc.y += (v0.y + v1.y) + (v2.y + v3.y);
    }
    for (; j < deg; j++) {
        int s = cp[j];
        if (act) {
            float2 v = *(const float2*)&H[(size_t)s * F + lane * 2];
            acc.x += v.x; acc.y += v.y;
        }
    }
    if (act) *(float2*)&AGG[(size_t)warp * F + lane * 2] = acc;
}

template<int F, int LAYER>
__global__ void ovf_scatter_kernel() {
    const float* __restrict__ H   = (LAYER == 1) ? g_h1   : g_h2;
    float* __restrict__       AGG = (LAYER == 1) ? g_agg1 : g_agg2;
    int cnt = g_ovf_cnt;
    if (cnt > OVF_CAP) cnt = OVF_CAP;
    int total = cnt * (F / 4);
    for (int i = blockIdx.x * blockDim.x + threadIdx.x; i < total;
         i += gridDim.x * blockDim.x) {
        int e = i / (F / 4);
        int q = (i - e * (F / 4)) * 4;
        int s = g_ovf_src[e], d = g_ovf_dst[e];
        float4 v = *(const float4*)&H[(size_t)s * F + q];
        red_add_f4(&AGG[(size_t)d * F + q], v);
    }
}

// ======== shared device helpers for tf32 fragment GEMM [R7 verbatim] ========
template<int K, int NT>
__device__ __forceinline__ void stage_B(const float* __restrict__ W, uint32_t* sB, int t) {
    constexpr int KT = K / 8;
    for (int i = t; i < KT * NT * 32; i += 256) {
        int l = i & 31;
        int tile = i >> 5;
        int nt = tile % NT, kt = tile / NT;
        int f  = nt * 8 + (l >> 2);
        int k0 = kt * 8 + (l & 3);
        sB[i * 2 + 0] = f2tf32(W[f * K + k0]);
        sB[i * 2 + 1] = f2tf32(W[f * K + k0 + 4]);
    }
}

template<int K, int PAD>
__device__ __forceinline__ void restage_A(const float* sAct, uint32_t* sF, int t) {
    constexpr int Q = K / 4;
    for (int i = t; i < 128 * Q; i += 256) {
        int n = i / Q, q = i - n * Q, k = q * 4;
        int wg = n >> 4, r = n & 15, kt = k >> 3, ki = k & 7;
        int reg = ((ki >> 2) << 1) | (r >> 3);
        int l0  = (r & 7) << 2;
        float4 v = *(const float4*)&sAct[n * PAD + k];
        uint4 u = make_uint4(f2tf32(v.x), f2tf32(v.y), f2tf32(v.z), f2tf32(v.w));
        *(uint4*)&sF[((kt * 8 + wg) * 4 + reg) * 32 + l0] = u;
    }
}

template<int K, int NT>
__device__ __forceinline__ void mma_stage(const uint32_t* sF, const uint32_t* sB,
                                          float acc[][4], int warp, int lane) {
    constexpr int KT = K / 8;
#pragma unroll
    for (int nt = 0; nt < NT; nt++)
#pragma unroll
        for (int j = 0; j < 4; j++) acc[nt][j] = 0.f;
#pragma unroll
    for (int kt = 0; kt < KT; kt++) {
        uint32_t a[4];
#pragma unroll
        for (int reg = 0; reg < 4; reg++)
            a[reg] = sF[((kt * 8 + warp) * 4 + reg) * 32 + lane];
#pragma unroll
        for (int nt = 0; nt < NT; nt++) {
            uint32_t b[2];
            *(float2*)b = *(const float2*)&sB[((kt * NT + nt) * 32 + lane) * 2];
            mma_tf32(acc[nt], a, b);
        }
    }
}

template<int NT, int PAD, bool RELU>
__device__ __forceinline__ void epi_to_smem(float acc[][4], const float* __restrict__ bias,
                                            float* sAct, int warp, int lane) {
    int row = lane >> 2;
    int cb  = (lane & 3) * 2;
    int r1 = warp * 16 + row, r2 = r1 + 8;
#pragma unroll
    for (int nt = 0; nt < NT; nt++) {
        int f = nt * 8 + cb;
        float bx = __ldg(bias + f), by = __ldg(bias + f + 1);
        float2 v1 = make_float2(acc[nt][0] + bx, acc[nt][1] + by);
        float2 v2 = make_float2(acc[nt][2] + bx, acc[nt][3] + by);
        if (RELU) {
            v1.x = fmaxf(v1.x, 0.f); v1.y = fmaxf(v1.y, 0.f);
            v2.x = fmaxf(v2.x, 0.f); v2.y = fmaxf(v2.y, 0.f);
        }
        *(float2*)&sAct[r1 * PAD + f] = v1;
        *(float2*)&sAct[r2 * PAD + f] = v2;
    }
}

template<int NT, int NF, bool RELU>
__device__ __forceinline__ void epi_to_gmem(float acc[][4], const float* __restrict__ bias,
                                            float* __restrict__ Y, int n0, int N,
                                            int warp, int lane) {
    int row = lane >> 2;
    int cb  = (lane & 3) * 2;
    int gn1 = n0 + warp * 16 + row;
    int gn2 = gn1 + 8;
#pragma unroll
    for (int nt = 0; nt < NT; nt++) {
        int f = nt * 8 + cb;
        float bx = __ldg(bias + f), by = __ldg(bias + f + 1);
        float2 v1 = make_float2(acc[nt][0] + bx, acc[nt][1] + by);
        float2 v2 = make_float2(acc[nt][2] + bx, acc[nt][3] + by);
        if (RELU) {
            v1.x = fmaxf(v1.x, 0.f); v1.y = fmaxf(v1.y, 0.f);
            v2.x = fmaxf(v2.x, 0.f); v2.y = fmaxf(v2.y, 0.f);
        }
        if (gn1 < N) *(float2*)&Y[(size_t)gn1 * NF + f] = v1;
        if (gn2 < N) *(float2*)&Y[(size_t)gn2 * NF + f] = v2;
    }
}

// ---------------- lin1: g_h1 = x @ W^T + b  (128 -> 64)  [R7 verbatim] ----------------
__global__ void __launch_bounds__(256)
lin1_mma(const float* __restrict__ X, const float* __restrict__ W,
         const float* __restrict__ bias, int N)
{
    constexpr int NT = 8;
    extern __shared__ float sm[];
    uint32_t* sF = (uint32_t*)sm;
    uint32_t* sB = sF + 8192;

    int t = threadIdx.x, warp = t >> 5, lane = t & 31;
    int n0 = blockIdx.x * 128;

    stage_B<128, NT>(W, sB, t);

    float acc[NT][4];
#pragma unroll
    for (int nt = 0; nt < NT; nt++)
#pragma unroll
        for (int j = 0; j < 4; j++) acc[nt][j] = 0.f;

    for (int ch = 0; ch < 2; ch++) {
        if (ch) __syncthreads();
        for (int i = t; i < 128 * 16; i += 256) {
            int n = i >> 4, q = i & 15, k = q * 4;
            int gn = n0 + n;
            float4 v = (gn < N) ? *(const float4*)&X[(size_t)gn * 128 + ch * 64 + k]
                                : make_float4(0.f, 0.f, 0.f, 0.f);
            int wg = n >> 4, r = n & 15, kt = k >> 3, ki = k & 7;
            int reg = ((ki >> 2) << 1) | (r >> 3);
            int l0  = (r & 7) << 2;
            uint4 u = make_uint4(f2tf32(v.x), f2tf32(v.y), f2tf32(v.z), f2tf32(v.w));
            *(uint4*)&sF[((kt * 8 + wg) * 4 + reg) * 32 + l0] = u;
        }
        __syncthreads();
#pragma unroll
        for (int kt = 0; kt < 8; kt++) {
            uint32_t a[4];
#pragma unroll
            for (int reg = 0; reg < 4; reg++)
                a[reg] = sF[((kt * 8 + warp) * 4 + reg) * 32 + lane];
#pragma unroll
            for (int nt = 0; nt < NT; nt++) {
                uint32_t b[2];
                *(float2*)b = *(const float2*)&sB[(((ch * 8 + kt) * NT + nt) * 32 + lane) * 2];
                mma_tf32(acc[nt], a, b);
            }
        }
    }
    epi_to_gmem<NT, 64, false>(acc, bias, g_h1, n0, N, warp, lane);
}

// ---------------- fused mid-MLP (single shared B buffer -> 84KB smem, 2 blk/SM) ----------------
__global__ void __launch_bounds__(256)
fused_mlp1(const float* __restrict__ W1, const float* __restrict__ b1,
           const float* __restrict__ W2, const float* __restrict__ b2,
           const float* __restrict__ W3, const float* __restrict__ b3, int N)
{
    constexpr int PAD = 68;
    extern __shared__ float sm[];
    float* sAct  = sm;                          // 128*68 floats = 34816 B
    uint32_t* sF = (uint32_t*)(sm + 128 * PAD); // 8192 u32 = 32768 B
    uint32_t* sB = sF + 8192;                   // 4096 u32 = 16384 B (shared, restaged)

    int t = threadIdx.x, warp = t >> 5, lane = t & 31;
    int n0 = blockIdx.x * 128;

    // stage W1 + relu(agg1) -> sAct
    stage_B<64, 8>(W1, sB, t);
    for (int i = t; i < 128 * 16; i += 256) {
        int n = i >> 4, q = i & 15;
        int gn = n0 + n;
        float4 v = (gn < N) ? *(const float4*)&g_agg1[(size_t)gn * 64 + q * 4]
                            : make_float4(0.f, 0.f, 0.f, 0.f);
        v.x = fmaxf(v.x, 0.f); v.y = fmaxf(v.y, 0.f);
        v.z = fmaxf(v.z, 0.f); v.w = fmaxf(v.w, 0.f);
        *(float4*)&sAct[n * PAD + q * 4] = v;
    }
    __syncthreads();

    float acc[8][4];

    // stage 1: relu(a@W1^T+b1) -> sAct
    restage_A<64, PAD>(sAct, sF, t);
    __syncthreads();
    mma_stage<64, 8>(sF, sB, acc, warp, lane);
    __syncthreads();                               // frag+B reads done
    epi_to_smem<8, PAD, true>(acc, b1, sAct, warp, lane);
    stage_B<64, 8>(W2, sB, t);
    __syncthreads();

    // stage 2: relu(b@W2^T+b2) -> sAct
    restage_A<64, PAD>(sAct, sF, t);
    __syncthreads();
    mma_stage<64, 8>(sF, sB, acc, warp, lane);
    __syncthreads();
    epi_to_smem<8, PAD, true>(acc, b2, sAct, warp, lane);
    stage_B<64, 5>(W3, sB, t);
    __syncthreads();

    // stage 3: c@W3^T+b3 -> g_h2 (64 -> 40)
    restage_A<64, PAD>(sAct, sF, t);
    __syncthreads();
    mma_stage<64, 5>(sF, sB, acc, warp, lane);
    epi_to_gmem<5, 40, false>(acc, b3, g_h2, n0, N, warp, lane);
}

// ---------------- fused final MLP  [R7 verbatim] ----------------
__global__ void __launch_bounds__(256)
fused_mlp2(const float* __restrict__ W1, const float* __restrict__ b1,
           const float* __restrict__ W2, const float* __restrict__ b2,
           float* __restrict__ out, int N)
{
    constexpr int PAD = 44;
    extern __shared__ float sm[];
    float* sAct   = sm;
    uint32_t* sF  = (uint32_t*)(sm + 128 * PAD);
    uint32_t* sB1 = sF + 5120;
    uint32_t* sB2 = sB1 + 1600;

    int t = threadIdx.x, warp = t >> 5, lane = t & 31;
    int n0 = blockIdx.x * 128;

    stage_B<40, 5>(W1, sB1, t);
    stage_B<40, 5>(W2, sB2, t);

    for (int i = t; i < 128 * 10; i += 256) {
        int n = i / 10, q = i - n * 10;
        int gn = n0 + n;
        float4 v = (gn < N) ? *(const float4*)&g_agg2[(size_t)gn * 40 + q * 4]
                            : make_float4(0.f, 0.f, 0.f, 0.f);
        v.x = fmaxf(v.x, 0.f); v.y = fmaxf(v.y, 0.f);
        v.z = fmaxf(v.z, 0.f); v.w = fmaxf(v.w, 0.f);
        *(float4*)&sAct[n * PAD + q * 4] = v;
    }
    __syncthreads();

    float acc[5][4];

    restage_A<40, PAD>(sAct, sF, t);
    __syncthreads();
    mma_stage<40, 5>(sF, sB1, acc, warp, lane);
    __syncthreads();
    epi_to_smem<5, PAD, true>(acc, b1, sAct, warp, lane);
    __syncthreads();

    restage_A<40, PAD>(sAct, sF, t);
    __syncthreads();
    mma_stage<40, 5>(sF, sB2, acc, warp, lane);
    epi_to_gmem<5, 40, false>(acc, b2, out, n0, N, warp, lane);
}

// ---------------- launch ----------------
extern "C" void kernel_launch(void* const* d_in, const int* in_sizes, int n_in,
                              void* d_out, int out_size) {
    const float*     x   = (const float*)d_in[0];
    const long long* idx = (const long long*)d_in[1];
    const float* w1_lin = (const float*)d_in[2];
    const float* b1_lin = (const float*)d_in[3];
    const float* w1_o1  = (const float*)d_in[4];
    const float* b1_o1  = (const float*)d_in[5];
    const float* w1_o2  = (const float*)d_in[6];
    const float* b1_o2  = (const float*)d_in[7];
    const float* w2_lin = (const float*)d_in[8];
    const float* b2_lin = (const float*)d_in[9];
    const float* w2_o1  = (const float*)d_in[10];
    const float* b2_o1  = (const float*)d_in[11];
    const float* w2_o2  = (const float*)d_in[12];
    const float* b2_o2  = (const float*)d_in[13];
    float* out = (float*)d_out;

    int N = in_sizes[0] / 128;
    int E = in_sizes[1] / 2;

    const int SM_LIN1 = (8192 + 8192) * 4;                        // 65536
    const int SM_MLP1 = (128 * 68 + 8192 + 4096) * 4;             // 83968
    const int SM_MLP2 = (128 * 44 + 5120 + 1600 + 1600) * 4;      // 55808

    cudaFuncSetAttribute(lin1_mma,   cudaFuncAttributeMaxDynamicSharedMemorySize, SM_LIN1);
    cudaFuncSetAttribute(fused_mlp1, cudaFuncAttributeMaxDynamicSharedMemorySize, SM_MLP1);
    cudaFuncSetAttribute(fused_mlp2, cudaFuncAttributeMaxDynamicSharedMemorySize, SM_MLP2);

    // one-time side stream + events for capture fork/join (infra only; the
    // launched WORK is identical on every call)
    static cudaStream_t s2 = nullptr;
    static cudaEvent_t evF = nullptr, evJ = nullptr;
    if (s2 == nullptr) {
        cudaStreamCreateWithFlags(&s2, cudaStreamNonBlocking);
        cudaEventCreateWithFlags(&evF, cudaEventDisableTiming);
        cudaEventCreateWithFlags(&evJ, cudaEventDisableTiming);
    }
    void *degPtr = nullptr, *ovfPtr = nullptr;
    cudaGetSymbolAddress(&degPtr, g_deg);     // true DEVICE address
    cudaGetSymbolAddress(&ovfPtr, g_ovf_cnt);

    int gemmBlocks = (N + 127) / 128;

    // fork: CSR build on side stream, concurrent with lin1 on main stream
    cudaEventRecord(evF, 0);
    cudaStreamWaitEvent(s2, evF, 0);
    cudaMemsetAsync(degPtr, 0, (size_t)N * sizeof(int), s2);
    cudaMemsetAsync(ovfPtr, 0, sizeof(int), s2);
    detect_idx_kernel<<<1, 32, 0, s2>>>(idx, E, (long long)N);
    csr_fill_kernel<<<(E + 255) / 256, 256, 0, s2>>>(idx, E);
    cudaEventRecord(evJ, s2);

    lin1_mma<<<gemmBlocks, 256, SM_LIN1>>>(x, w1_lin, b1_lin, N);

    // join: gather needs both lin1 (h1) and the CSR
    cudaStreamWaitEvent(0, evJ, 0);

    gather_kernel<64, 1><<<(N + 7) / 8, 256>>>(N);
    ovf_scatter_kernel<64, 1><<<64, 128>>>();
    fused_mlp1<<<gemmBlocks, 256, SM_MLP1>>>(w1_o1, b1_o1, w1_o2, b1_o2,
                                             w2_lin, b2_lin, N);

    gather_kernel<40, 2><<<(N + 7) / 8, 256>>>(N);
    ovf_scatter_kernel<40, 2><<<64, 128>>>();
    fused_mlp2<<<gemmBlocks, 256, SM_MLP2>>>(w2_o1, b2_o1, w2_o2, b2_o2, out, N);
}

// round 9
// speedup vs baseline: 18.0496x; 1.0528x over previous
#include <cuda_runtime.h>
#include <cstdint>

#define NMAX 100000
#define EMAX 1000000
#define CAP 96
#define OVF_CAP 8192

// ---------------- scratch (no allocations allowed) ----------------
// NOTE: symbols ONLY referenced from device code, except via
// cudaGetSymbolAddress (true device address) for memset nodes.
__device__ float g_h1[NMAX * 64];    // lin1 output
__device__ float g_agg1[NMAX * 64];  // layer-1 aggregation
__device__ float g_h2[NMAX * 40];    // fused mid-MLP output
__device__ float g_agg2[NMAX * 40];  // layer-2 aggregation
__device__ int   g_deg[NMAX];
__device__ int   g_col[(size_t)NMAX * CAP];
__device__ int   g_ovf_cnt;
__device__ int   g_ovf_src[OVF_CAP];
__device__ int   g_ovf_dst[OVF_CAP];
__device__ int   g_idx32;

__device__ __forceinline__ void red_add_f4(float* p, float4 v) {
    asm volatile("red.global.add.v4.f32 [%0], {%1,%2,%3,%4};"
                 :: "l"(p), "f"(v.x), "f"(v.y), "f"(v.z), "f"(v.w)
                 : "memory");
}

__device__ __forceinline__ uint32_t f2tf32(float x) {
    uint32_t r;
    asm("cvt.rna.tf32.f32 %0, %1;" : "=r"(r) : "f"(x));
    return r;
}

__device__ __forceinline__ void mma_tf32(float* d, const uint32_t* a, const uint32_t* b) {
    asm volatile(
        "mma.sync.aligned.m16n8k8.row.col.f32.tf32.tf32.f32 "
        "{%0,%1,%2,%3}, {%4,%5,%6,%7}, {%8,%9}, {%0,%1,%2,%3};"
        : "+f"(d[0]), "+f"(d[1]), "+f"(d[2]), "+f"(d[3])
        : "r"(a[0]), "r"(a[1]), "r"(a[2]), "r"(a[3]), "r"(b[0]), "r"(b[1]));
}

// ---------------- dtype probe ----------------
__global__ void detect_idx_kernel(const long long* __restrict__ idx, int E, long long N) {
    if (blockIdx.x == 0 && threadIdx.x == 0) {
        int is32 = 0;
        int nc = E < 64 ? E : 64;
        for (int i = 0; i < nc; i++) {
            long long v = idx[i];
            if (v < 0 || v >= N) { is32 = 1; break; }
        }
        g_idx32 = is32;
    }
}

__global__ void csr_fill_kernel(const long long* __restrict__ idx, int E) {
    int e = blockIdx.x * blockDim.x + threadIdx.x;
    if (e >= E) return;
    int s, d;
    if (g_idx32) {
        const int* p = (const int*)idx;
        s = p[e]; d = p[E + e];
    } else {
        s = (int)idx[e]; d = (int)idx[E + e];
    }
    int slot = atomicAdd(&g_deg[d], 1);
    if (slot < CAP) {
        g_col[(size_t)d * CAP + slot] = s;
    } else {
        int o = atomicAdd(&g_ovf_cnt, 1);
        if (o < OVF_CAP) { g_ovf_src[o] = s; g_ovf_dst[o] = d; }
    }
}

// ---------------- gather F=64: 2 nodes/warp, float4 lanes ----------------
__global__ void gather64_kernel(int N) {
    int gw   = (int)((blockIdx.x * (long long)blockDim.x + threadIdx.x) >> 5);
    int lane = threadIdx.x & 31;
    int node = gw * 2 + (lane >> 4);
    int sl   = lane & 15;
    if (node >= N) return;

    float4 acc = *(const float4*)&g_h1[(size_t)node * 64 + sl * 4];  // self-loop
    int deg = g_deg[node];
    if (deg > CAP) deg = CAP;
    const int* cp = g_col + (size_t)node * CAP;
    int j = 0;
    for (; j + 4 <= deg; j += 4) {
        int4 s = *(const int4*)&cp[j];
        float4 v0 = *(const float4*)&g_h1[(size_t)s.x * 64 + sl * 4];
        float4 v1 = *(const float4*)&g_h1[(size_t)s.y * 64 + sl * 4];
        float4 v2 = *(const float4*)&g_h1[(size_t)s.z * 64 + sl * 4];
        float4 v3 = *(const float4*)&g_h1[(size_t)s.w * 64 + sl * 4];
        acc.x += (v0.x + v1.x) + (v2.x + v3.x);
        acc.y += (v0.y + v1.y) + (v2.y + v3.y);
        acc.z += (v0.z + v1.z) + (v2.z + v3.z);
        acc.w += (v0.w + v1.w) + (v2.w + v3.w);
    }
    for (; j < deg; j++) {
        int s = cp[j];
        float4 v = *(const float4*)&g_h1[(size_t)s * 64 + sl * 4];
        acc.x += v.x; acc.y += v.y; acc.z += v.z; acc.w += v.w;
    }
    *(float4*)&g_agg1[(size_t)node * 64 + sl * 4] = acc;
}

// ---------------- gather F=40: 3 nodes/warp, float4 lanes (10 per node) ----------------
__global__ void gather40_kernel(int N) {
    int gw   = (int)((blockIdx.x * (long long)blockDim.x + threadIdx.x) >> 5);
    int lane = threadIdx.x & 31;
    int sub  = (lane * 13) >> 7;          // lane/10 for lane<40
    int sl   = lane - sub * 10;
    if (sub >= 3) return;
    int node = gw * 3 + sub;
    if (node >= N) return;

    float4 acc = *(const float4*)&g_h2[(size_t)node * 40 + sl * 4];  // self-loop
    int deg = g_deg[node];
    if (deg > CAP) deg = CAP;
    const int* cp = g_col + (size_t)node * CAP;
    int j = 0;
    for (; j + 4 <= deg; j += 4) {
        int4 s = *(const int4*)&cp[j];
        float4 v0 = *(const float4*)&g_h2[(size_t)s.x * 40 + sl * 4];
        float4 v1 = *(const float4*)&g_h2[(size_t)s.y * 40 + sl * 4];
        float4 v2 = *(const float4*)&g_h2[(size_t)s.z * 40 + sl * 4];
        float4 v3 = *(const float4*)&g_h2[(size_t)s.w * 40 + sl * 4];
        acc.x += (v0.x + v1.x) + (v2.x + v3.x);
        acc.y += (v0.y + v1.y) + (v2.y + v3.y);
        acc.z += (v0.z + v1.z) + (v2.z + v3.z);
        acc.w += (v0.w + v1.w) + (v2.w + v3.w);
    }
    for (; j < deg; j++) {
        int s = cp[j];
        float4 v = *(const float4*)&g_h2[(size_t)s * 40 + sl * 4];
        acc.x += v.x; acc.y += v.y; acc.z += v.z; acc.w += v.w;
    }
    *(float4*)&g_agg2[(size_t)node * 40 + sl * 4] = acc;
}

template<int F, int LAYER>
__global__ void ovf_scatter_kernel() {
    const float* __restrict__ H   = (LAYER == 1) ? g_h1   : g_h2;
    float* __restrict__       AGG = (LAYER == 1) ? g_agg1 : g_agg2;
    int cnt = g_ovf_cnt;
    if (cnt > OVF_CAP) cnt = OVF_CAP;
    int total = cnt * (F / 4);
    for (int i = blockIdx.x * blockDim.x + threadIdx.x; i < total;
         i += gridDim.x * blockDim.x) {
        int e = i / (F / 4);
        int q = (i - e * (F / 4)) * 4;
        int s = g_ovf_src[e], d = g_ovf_dst[e];
        float4 v = *(const float4*)&H[(size_t)s * F + q];
        red_add_f4(&AGG[(size_t)d * F + q], v);
    }
}

// ======== shared device helpers for tf32 fragment GEMM [R7 verbatim] ========
template<int K, int NT>
__device__ __forceinline__ void stage_B(const float* __restrict__ W, uint32_t* sB, int t) {
    constexpr int KT = K / 8;
    for (int i = t; i < KT * NT * 32; i += 256) {
        int l = i & 31;
        int tile = i >> 5;
        int nt = tile % NT, kt = tile / NT;
        int f  = nt * 8 + (l >> 2);
        int k0 = kt * 8 + (l & 3);
        sB[i * 2 + 0] = f2tf32(W[f * K + k0]);
        sB[i * 2 + 1] = f2tf32(W[f * K + k0 + 4]);
    }
}

template<int K, int PAD>
__device__ __forceinline__ void restage_A(const float* sAct, uint32_t* sF, int t) {
    constexpr int Q = K / 4;
    for (int i = t; i < 128 * Q; i += 256) {
        int n = i / Q, q = i - n * Q, k = q * 4;
        int wg = n >> 4, r = n & 15, kt = k >> 3, ki = k & 7;
        int reg = ((ki >> 2) << 1) | (r >> 3);
        int l0  = (r & 7) << 2;
        float4 v = *(const float4*)&sAct[n * PAD + k];
        uint4 u = make_uint4(f2tf32(v.x), f2tf32(v.y), f2tf32(v.z), f2tf32(v.w));
        *(uint4*)&sF[((kt * 8 + wg) * 4 + reg) * 32 + l0] = u;
    }
}

template<int K, int NT>
__device__ __forceinline__ void mma_stage(const uint32_t* sF, const uint32_t* sB,
                                          float acc[][4], int warp, int lane) {
    constexpr int KT = K / 8;
#pragma unroll
    for (int nt = 0; nt < NT; nt++)
#pragma unroll
        for (int j = 0; j < 4; j++) acc[nt][j] = 0.f;
#pragma unroll
    for (int kt = 0; kt < KT; kt++) {
        uint32_t a[4];
#pragma unroll
        for (int reg = 0; reg < 4; reg++)
            a[reg] = sF[((kt * 8 + warp) * 4 + reg) * 32 + lane];
#pragma unroll
        for (int nt = 0; nt < NT; nt++) {
            uint32_t b[2];
            *(float2*)b = *(const float2*)&sB[((kt * NT + nt) * 32 + lane) * 2];
            mma_tf32(acc[nt], a, b);
        }
    }
}

template<int NT, int PAD, bool RELU>
__device__ __forceinline__ void epi_to_smem(float acc[][4], const float* __restrict__ bias,
                                            float* sAct, int warp, int lane) {
    int row = lane >> 2;
    int cb  = (lane & 3) * 2;
    int r1 = warp * 16 + row, r2 = r1 + 8;
#pragma unroll
    for (int nt = 0; nt < NT; nt++) {
        int f = nt * 8 + cb;
        float bx = __ldg(bias + f), by = __ldg(bias + f + 1);
        float2 v1 = make_float2(acc[nt][0] + bx, acc[nt][1] + by);
        float2 v2 = make_float2(acc[nt][2] + bx, acc[nt][3] + by);
        if (RELU) {
            v1.x = fmaxf(v1.x, 0.f); v1.y = fmaxf(v1.y, 0.f);
            v2.x = fmaxf(v2.x, 0.f); v2.y = fmaxf(v2.y, 0.f);
        }
        *(float2*)&sAct[r1 * PAD + f] = v1;
        *(float2*)&sAct[r2 * PAD + f] = v2;
    }
}

template<int NT, int NF, bool RELU>
__device__ __forceinline__ void epi_to_gmem(float acc[][4], const float* __restrict__ bias,
                                            float* __restrict__ Y, int n0, int N,
                                            int warp, int lane) {
    int row = lane >> 2;
    int cb  = (lane & 3) * 2;
    int gn1 = n0 + warp * 16 + row;
    int gn2 = gn1 + 8;
#pragma unroll
    for (int nt = 0; nt < NT; nt++) {
        int f = nt * 8 + cb;
        float bx = __ldg(bias + f), by = __ldg(bias + f + 1);
        float2 v1 = make_float2(acc[nt][0] + bx, acc[nt][1] + by);
        float2 v2 = make_float2(acc[nt][2] + bx, acc[nt][3] + by);
        if (RELU) {
            v1.x = fmaxf(v1.x, 0.f); v1.y = fmaxf(v1.y, 0.f);
            v2.x = fmaxf(v2.x, 0.f); v2.y = fmaxf(v2.y, 0.f);
        }
        if (gn1 < N) *(float2*)&Y[(size_t)gn1 * NF + f] = v1;
        if (gn2 < N) *(float2*)&Y[(size_t)gn2 * NF + f] = v2;
    }
}

// ---------------- lin1: g_h1 = x @ W^T + b  (128 -> 64)  [R7 verbatim] ----------------
__global__ void __launch_bounds__(256)
lin1_mma(const float* __restrict__ X, const float* __restrict__ W,
         const float* __restrict__ bias, int N)
{
    constexpr int NT = 8;
    extern __shared__ float sm[];
    uint32_t* sF = (uint32_t*)sm;
    uint32_t* sB = sF + 8192;

    int t = threadIdx.x, warp = t >> 5, lane = t & 31;
    int n0 = blockIdx.x * 128;

    stage_B<128, NT>(W, sB, t);

    float acc[NT][4];
#pragma unroll
    for (int nt = 0; nt < NT; nt++)
#pragma unroll
        for (int j = 0; j < 4; j++) acc[nt][j] = 0.f;

    for (int ch = 0; ch < 2; ch++) {
        if (ch) __syncthreads();
        for (int i = t; i < 128 * 16; i += 256) {
            int n = i >> 4, q = i & 15, k = q * 4;
            int gn = n0 + n;
            float4 v = (gn < N) ? *(const float4*)&X[(size_t)gn * 128 + ch * 64 + k]
                                : make_float4(0.f, 0.f, 0.f, 0.f);
            int wg = n >> 4, r = n & 15, kt = k >> 3, ki = k & 7;
            int reg = ((ki >> 2) << 1) | (r >> 3);
            int l0  = (r & 7) << 2;
            uint4 u = make_uint4(f2tf32(v.x), f2tf32(v.y), f2tf32(v.z), f2tf32(v.w));
            *(uint4*)&sF[((kt * 8 + wg) * 4 + reg) * 32 + l0] = u;
        }
        __syncthreads();
#pragma unroll
        for (int kt = 0; kt < 8; kt++) {
            uint32_t a[4];
#pragma unroll
            for (int reg = 0; reg < 4; reg++)
                a[reg] = sF[((kt * 8 + warp) * 4 + reg) * 32 + lane];
#pragma unroll
            for (int nt = 0; nt < NT; nt++) {
                uint32_t b[2];
                *(float2*)b = *(const float2*)&sB[(((ch * 8 + kt) * NT + nt) * 32 + lane) * 2];
                mma_tf32(acc[nt], a, b);
            }
        }
    }
    epi_to_gmem<NT, 64, false>(acc, bias, g_h1, n0, N, warp, lane);
}

// ---------------- fused mid-MLP  [R8 verbatim] ----------------
__global__ void __launch_bounds__(256)
fused_mlp1(const float* __restrict__ W1, const float* __restrict__ b1,
           const float* __restrict__ W2, const float* __restrict__ b2,
           const float* __restrict__ W3, const float* __restrict__ b3, int N)
{
    constexpr int PAD = 68;
    extern __shared__ float sm[];
    float* sAct  = sm;
    uint32_t* sF = (uint32_t*)(sm + 128 * PAD);
    uint32_t* sB = sF + 8192;

    int t = threadIdx.x, warp = t >> 5, lane = t & 31;
    int n0 = blockIdx.x * 128;

    stage_B<64, 8>(W1, sB, t);
    for (int i = t; i < 128 * 16; i += 256) {
        int n = i >> 4, q = i & 15;
        int gn = n0 + n;
        float4 v = (gn < N) ? *(const float4*)&g_agg1[(size_t)gn * 64 + q * 4]
                            : make_float4(0.f, 0.f, 0.f, 0.f);
        v.x = fmaxf(v.x, 0.f); v.y = fmaxf(v.y, 0.f);
        v.z = fmaxf(v.z, 0.f); v.w = fmaxf(v.w, 0.f);
        *(float4*)&sAct[n * PAD + q * 4] = v;
    }
    __syncthreads();

    float acc[8][4];

    restage_A<64, PAD>(sAct, sF, t);
    __syncthreads();
    mma_stage<64, 8>(sF, sB, acc, warp, lane);
    __syncthreads();
    epi_to_smem<8, PAD, true>(acc, b1, sAct, warp, lane);
    stage_B<64, 8>(W2, sB, t);
    __syncthreads();

    restage_A<64, PAD>(sAct, sF, t);
    __syncthreads();
    mma_stage<64, 8>(sF, sB, acc, warp, lane);
    __syncthreads();
    epi_to_smem<8, PAD, true>(acc, b2, sAct, warp, lane);
    stage_B<64, 5>(W3, sB, t);
    __syncthreads();

    restage_A<64, PAD>(sAct, sF, t);
    __syncthreads();
    mma_stage<64, 5>(sF, sB, acc, warp, lane);
    epi_to_gmem<5, 40, false>(acc, b3, g_h2, n0, N, warp, lane);
}

// ---------------- fused final MLP  [R7 verbatim] ----------------
__global__ void __launch_bounds__(256)
fused_mlp2(const float* __restrict__ W1, const float* __restrict__ b1,
           const float* __restrict__ W2, const float* __restrict__ b2,
           float* __restrict__ out, int N)
{
    constexpr int PAD = 44;
    extern __shared__ float sm[];
    float* sAct   = sm;
    uint32_t* sF  = (uint32_t*)(sm + 128 * PAD);
    uint32_t* sB1 = sF + 5120;
    uint32_t* sB2 = sB1 + 1600;

    int t = threadIdx.x, warp = t >> 5, lane = t & 31;
    int n0 = blockIdx.x * 128;

    stage_B<40, 5>(W1, sB1, t);
    stage_B<40, 5>(W2, sB2, t);

    for (int i = t; i < 128 * 10; i += 256) {
        int n = i / 10, q = i - n * 10;
        int gn = n0 + n;
        float4 v = (gn < N) ? *(const float4*)&g_agg2[(size_t)gn * 40 + q * 4]
                            : make_float4(0.f, 0.f, 0.f, 0.f);
        v.x = fmaxf(v.x, 0.f); v.y = fmaxf(v.y, 0.f);
        v.z = fmaxf(v.z, 0.f); v.w = fmaxf(v.w, 0.f);
        *(float4*)&sAct[n * PAD + q * 4] = v;
    }
    __syncthreads();

    float acc[5][4];

    restage_A<40, PAD>(sAct, sF, t);
    __syncthreads();
    mma_stage<40, 5>(sF, sB1, acc, warp, lane);
    __syncthreads();
    epi_to_smem<5, PAD, true>(acc, b1, sAct, warp, lane);
    __syncthreads();

    restage_A<40, PAD>(sAct, sF, t);
    __syncthreads();
    mma_stage<40, 5>(sF, sB2, acc, warp, lane);
    epi_to_gmem<5, 40, false>(acc, b2, out, n0, N, warp, lane);
}

// ---------------- launch ----------------
extern "C" void kernel_launch(void* const* d_in, const int* in_sizes, int n_in,
                              void* d_out, int out_size) {
    const float*     x   = (const float*)d_in[0];
    const long long* idx = (const long long*)d_in[1];
    const float* w1_lin = (const float*)d_in[2];
    const float* b1_lin = (const float*)d_in[3];
    const float* w1_o1  = (const float*)d_in[4];
    const float* b1_o1  = (const float*)d_in[5];
    const float* w1_o2  = (const float*)d_in[6];
    const float* b1_o2  = (const float*)d_in[7];
    const float* w2_lin = (const float*)d_in[8];
    const float* b2_lin = (const float*)d_in[9];
    const float* w2_o1  = (const float*)d_in[10];
    const float* b2_o1  = (const float*)d_in[11];
    const float* w2_o2  = (const float*)d_in[12];
    const float* b2_o2  = (const float*)d_in[13];
    float* out = (float*)d_out;

    int N = in_sizes[0] / 128;
    int E = in_sizes[1] / 2;

    const int SM_LIN1 = (8192 + 8192) * 4;                        // 65536
    const int SM_MLP1 = (128 * 68 + 8192 + 4096) * 4;             // 83968
    const int SM_MLP2 = (128 * 44 + 5120 + 1600 + 1600) * 4;      // 55808

    cudaFuncSetAttribute(lin1_mma,   cudaFuncAttributeMaxDynamicSharedMemorySize, SM_LIN1);
    cudaFuncSetAttribute(fused_mlp1, cudaFuncAttributeMaxDynamicSharedMemorySize, SM_MLP1);
    cudaFuncSetAttribute(fused_mlp2, cudaFuncAttributeMaxDynamicSharedMemorySize, SM_MLP2);

    static cudaStream_t s2 = nullptr;
    static cudaEvent_t evF = nullptr, evJ = nullptr;
    if (s2 == nullptr) {
        cudaStreamCreateWithFlags(&s2, cudaStreamNonBlocking);
        cudaEventCreateWithFlags(&evF, cudaEventDisableTiming);
        cudaEventCreateWithFlags(&evJ, cudaEventDisableTiming);
    }
    void *degPtr = nullptr, *ovfPtr = nullptr;
    cudaGetSymbolAddress(&degPtr, g_deg);
    cudaGetSymbolAddress(&ovfPtr, g_ovf_cnt);

    int gemmBlocks = (N + 127) / 128;

    // fork: CSR build on side stream, concurrent with lin1 on main stream
    cudaEventRecord(evF, 0);
    cudaStreamWaitEvent(s2, evF, 0);
    cudaMemsetAsync(degPtr, 0, (size_t)N * sizeof(int), s2);
    cudaMemsetAsync(ovfPtr, 0, sizeof(int), s2);
    detect_idx_kernel<<<1, 32, 0, s2>>>(idx, E, (long long)N);
    csr_fill_kernel<<<(E + 255) / 256, 256, 0, s2>>>(idx, E);
    cudaEventRecord(evJ, s2);

    lin1_mma<<<gemmBlocks, 256, SM_LIN1>>>(x, w1_lin, b1_lin, N);

    cudaStreamWaitEvent(0, evJ, 0);

    // layer 1: gather (2 nodes/warp) + mlp
    int w64 = (N + 1) / 2;                       // warps needed
    gather64_kernel<<<(w64 + 7) / 8, 256>>>(N);
    ovf_scatter_kernel<64, 1><<<64, 128>>>();
    fused_mlp1<<<gemmBlocks, 256, SM_MLP1>>>(w1_o1, b1_o1, w1_o2, b1_o2,
                                             w2_lin, b2_lin, N);

    // layer 2: gather (3 nodes/warp) + mlp
    int w40 = (N + 2) / 3;
    gather40_kernel<<<(w40 + 7) / 8, 256>>>(N);
    ovf_scatter_kernel<40, 2><<<64, 128>>>();
    fused_mlp2<<<gemmBlocks, 256, SM_MLP2>>>(w2_o1, b2_o1, w2_o2, b2_o2, out, N);
}

// round 10
// speedup vs baseline: 21.8014x; 1.2079x over previous
#include <cuda_runtime.h>
#include <cstdint>

#define NMAX 100000
#define EMAX 1000000
#define CAP 96
#define OVF_CAP 8192

// ---------------- scratch (no allocations allowed) ----------------
// NOTE: symbols ONLY referenced from device code, except via
// cudaGetSymbolAddress (true device address) for memset nodes.
__device__ float g_h1[NMAX * 64];    // lin1 output
__device__ float g_agg1[NMAX * 64];  // layer-1 aggregation
__device__ float g_h2[NMAX * 40];    // fused mid-MLP output
__device__ float g_agg2[NMAX * 40];  // layer-2 aggregation
__device__ int   g_deg[NMAX];
__device__ int   g_col[(size_t)NMAX * CAP];
__device__ int   g_ovf_cnt;
__device__ int   g_ovf_src[OVF_CAP];
__device__ int   g_ovf_dst[OVF_CAP];
__device__ int   g_idx32;

__device__ __forceinline__ void red_add_f4(float* p, float4 v) {
    asm volatile("red.global.add.v4.f32 [%0], {%1,%2,%3,%4};"
                 :: "l"(p), "f"(v.x), "f"(v.y), "f"(v.z), "f"(v.w)
                 : "memory");
}

__device__ __forceinline__ uint32_t f2tf32(float x) {
    uint32_t r;
    asm("cvt.rna.tf32.f32 %0, %1;" : "=r"(r) : "f"(x));
    return r;
}

__device__ __forceinline__ void mma_tf32(float* d, const uint32_t* a, const uint32_t* b) {
    asm volatile(
        "mma.sync.aligned.m16n8k8.row.col.f32.tf32.tf32.f32 "
        "{%0,%1,%2,%3}, {%4,%5,%6,%7}, {%8,%9}, {%0,%1,%2,%3};"
        : "+f"(d[0]), "+f"(d[1]), "+f"(d[2]), "+f"(d[3])
        : "r"(a[0]), "r"(a[1]), "r"(a[2]), "r"(a[3]), "r"(b[0]), "r"(b[1]));
}

// ---------------- dtype probe ----------------
__global__ void detect_idx_kernel(const long long* __restrict__ idx, int E, long long N) {
    if (blockIdx.x == 0 && threadIdx.x == 0) {
        int is32 = 0;
        int nc = E < 64 ? E : 64;
        for (int i = 0; i < nc; i++) {
            long long v = idx[i];
            if (v < 0 || v >= N) { is32 = 1; break; }
        }
        g_idx32 = is32;
    }
}

__global__ void csr_fill_kernel(const long long* __restrict__ idx, int E) {
    int e = blockIdx.x * blockDim.x + threadIdx.x;
    if (e >= E) return;
    int s, d;
    if (g_idx32) {
        const int* p = (const int*)idx;
        s = p[e]; d = p[E + e];
    } else {
        s = (int)idx[e]; d = (int)idx[E + e];
    }
    int slot = atomicAdd(&g_deg[d], 1);
    if (slot < CAP) {
        g_col[(size_t)d * CAP + slot] = s;
    } else {
        int o = atomicAdd(&g_ovf_cnt, 1);
        if (o < OVF_CAP) { g_ovf_src[o] = s; g_ovf_dst[o] = d; }
    }
}

// ---------------- gather F=64: 2 nodes/warp, float4 lanes, unroll 8 ----------------
__global__ void gather64_kernel(int N) {
    int gw   = (int)((blockIdx.x * (long long)blockDim.x + threadIdx.x) >> 5);
    int lane = threadIdx.x & 31;
    int node = gw * 2 + (lane >> 4);
    int sl   = lane & 15;
    if (node >= N) return;

    float4 acc = *(const float4*)&g_h1[(size_t)node * 64 + sl * 4];  // self-loop
    int deg = g_deg[node];
    if (deg > CAP) deg = CAP;
    const int* cp = g_col + (size_t)node * CAP;
    int j = 0;
    for (; j + 8 <= deg; j += 8) {
        int4 sa = *(const int4*)&cp[j];
        int4 sb = *(const int4*)&cp[j + 4];
        float4 v0 = *(const float4*)&g_h1[(size_t)sa.x * 64 + sl * 4];
        float4 v1 = *(const float4*)&g_h1[(size_t)sa.y * 64 + sl * 4];
        float4 v2 = *(const float4*)&g_h1[(size_t)sa.z * 64 + sl * 4];
        float4 v3 = *(const float4*)&g_h1[(size_t)sa.w * 64 + sl * 4];
        float4 v4 = *(const float4*)&g_h1[(size_t)sb.x * 64 + sl * 4];
        float4 v5 = *(const float4*)&g_h1[(size_t)sb.y * 64 + sl * 4];
        float4 v6 = *(const float4*)&g_h1[(size_t)sb.z * 64 + sl * 4];
        float4 v7 = *(const float4*)&g_h1[(size_t)sb.w * 64 + sl * 4];
        acc.x += ((v0.x + v1.x) + (v2.x + v3.x)) + ((v4.x + v5.x) + (v6.x + v7.x));
        acc.y += ((v0.y + v1.y) + (v2.y + v3.y)) + ((v4.y + v5.y) + (v6.y + v7.y));
        acc.z += ((v0.z + v1.z) + (v2.z + v3.z)) + ((v4.z + v5.z) + (v6.z + v7.z));
        acc.w += ((v0.w + v1.w) + (v2.w + v3.w)) + ((v4.w + v5.w) + (v6.w + v7.w));
    }
    for (; j + 4 <= deg; j += 4) {
        int4 s = *(const int4*)&cp[j];
        float4 v0 = *(const float4*)&g_h1[(size_t)s.x * 64 + sl * 4];
        float4 v1 = *(const float4*)&g_h1[(size_t)s.y * 64 + sl * 4];
        float4 v2 = *(const float4*)&g_h1[(size_t)s.z * 64 + sl * 4];
        float4 v3 = *(const float4*)&g_h1[(size_t)s.w * 64 + sl * 4];
        acc.x += (v0.x + v1.x) + (v2.x + v3.x);
        acc.y += (v0.y + v1.y) + (v2.y + v3.y);
        acc.z += (v0.z + v1.z) + (v2.z + v3.z);
        acc.w += (v0.w + v1.w) + (v2.w + v3.w);
    }
    for (; j < deg; j++) {
        int s = cp[j];
        float4 v = *(const float4*)&g_h1[(size_t)s * 64 + sl * 4];
        acc.x += v.x; acc.y += v.y; acc.z += v.z; acc.w += v.w;
    }
    *(float4*)&g_agg1[(size_t)node * 64 + sl * 4] = acc;
}

// ---------------- gather F=40: 3 nodes/warp, float4 lanes, unroll 8 ----------------
__global__ void gather40_kernel(int N) {
    int gw   = (int)((blockIdx.x * (long long)blockDim.x + threadIdx.x) >> 5);
    int lane = threadIdx.x & 31;
    int sub  = (lane * 13) >> 7;          // lane/10 for lane<40
    int sl   = lane - sub * 10;
    if (sub >= 3) return;
    int node = gw * 3 + sub;
    if (node >= N) return;

    float4 acc = *(const float4*)&g_h2[(size_t)node * 40 + sl * 4];  // self-loop
    int deg = g_deg[node];
    if (deg > CAP) deg = CAP;
    const int* cp = g_col + (size_t)node * CAP;
    int j = 0;
    for (; j + 8 <= deg; j += 8) {
        int4 sa = *(const int4*)&cp[j];
        int4 sb = *(const int4*)&cp[j + 4];
        float4 v0 = *(const float4*)&g_h2[(size_t)sa.x * 40 + sl * 4];
        float4 v1 = *(const float4*)&g_h2[(size_t)sa.y * 40 + sl * 4];
        float4 v2 = *(const float4*)&g_h2[(size_t)sa.z * 40 + sl * 4];
        float4 v3 = *(const float4*)&g_h2[(size_t)sa.w * 40 + sl * 4];
        float4 v4 = *(const float4*)&g_h2[(size_t)sb.x * 40 + sl * 4];
        float4 v5 = *(const float4*)&g_h2[(size_t)sb.y * 40 + sl * 4];
        float4 v6 = *(const float4*)&g_h2[(size_t)sb.z * 40 + sl * 4];
        float4 v7 = *(const float4*)&g_h2[(size_t)sb.w * 40 + sl * 4];
        acc.x += ((v0.x + v1.x) + (v2.x + v3.x)) + ((v4.x + v5.x) + (v6.x + v7.x));
        acc.y += ((v0.y + v1.y) + (v2.y + v3.y)) + ((v4.y + v5.y) + (v6.y + v7.y));
        acc.z += ((v0.z + v1.z) + (v2.z + v3.z)) + ((v4.z + v5.z) + (v6.z + v7.z));
        acc.w += ((v0.w + v1.w) + (v2.w + v3.w)) + ((v4.w + v5.w) + (v6.w + v7.w));
    }
    for (; j + 4 <= deg; j += 4) {
        int4 s = *(const int4*)&cp[j];
        float4 v0 = *(const float4*)&g_h2[(size_t)s.x * 40 + sl * 4];
        float4 v1 = *(const float4*)&g_h2[(size_t)s.y * 40 + sl * 4];
        float4 v2 = *(const float4*)&g_h2[(size_t)s.z * 40 + sl * 4];
        float4 v3 = *(const float4*)&g_h2[(size_t)s.w * 40 + sl * 4];
        acc.x += (v0.x + v1.x) + (v2.x + v3.x);
        acc.y += (v0.y + v1.y) + (v2.y + v3.y);
        acc.z += (v0.z + v1.z) + (v2.z + v3.z);
        acc.w += (v0.w + v1.w) + (v2.w + v3.w);
    }
    for (; j < deg; j++) {
        int s = cp[j];
        float4 v = *(const float4*)&g_h2[(size_t)s * 40 + sl * 4];
        acc.x += v.x; acc.y += v.y; acc.z += v.z; acc.w += v.w;
    }
    *(float4*)&g_agg2[(size_t)node * 40 + sl * 4] = acc;
}

template<int F, int LAYER>
__global__ void ovf_scatter_kernel() {
    const float* __restrict__ H   = (LAYER == 1) ? g_h1   : g_h2;
    float* __restrict__       AGG = (LAYER == 1) ? g_agg1 : g_agg2;
    int cnt = g_ovf_cnt;
    if (cnt > OVF_CAP) cnt = OVF_CAP;
    int total = cnt * (F / 4);
    for (int i = blockIdx.x * blockDim.x + threadIdx.x; i < total;
         i += gridDim.x * blockDim.x) {
        int e = i / (F / 4);
        int q = (i - e * (F / 4)) * 4;
        int s = g_ovf_src[e], d = g_ovf_dst[e];
        float4 v = *(const float4*)&H[(size_t)s * F + q];
        red_add_f4(&AGG[(size_t)d * F + q], v);
    }
}

// ======== tf32 fragment GEMM helpers ========
// B fragments (conflict-free): sB[((kt*NT + nt)*32 + lane)*2 + {0,1}]
template<int K, int NT>
__device__ __forceinline__ void stage_B(const float* __restrict__ W, uint32_t* sB, int t) {
    constexpr int KT = K / 8;
    for (int i = t; i < KT * NT * 32; i += 256) {
        int l = i & 31;
        int tile = i >> 5;
        int nt = tile % NT, kt = tile / NT;
        int f  = nt * 8 + (l >> 2);
        int k0 = kt * 8 + (l & 3);
        sB[i * 2 + 0] = f2tf32(W[f * K + k0]);
        sB[i * 2 + 1] = f2tf32(W[f * K + k0 + 4]);
    }
}

// MMA reading A directly from row-major padded sAct (PAD % 32 must give
// conflict-free 4g+c pattern; PAD=68 and PAD=44 both verified).
// a0=[g][c], a1=[g+8][c], a2=[g][c+4], a3=[g+8][c+4] per k-tile.
template<int K, int NT, int PAD, bool ZERO>
__device__ __forceinline__ void mma_direct(const float* sAct, const uint32_t* sB,
                                           float acc[][4], int warp, int lane) {
    constexpr int KT = K / 8;
    int g = lane >> 2, c = lane & 3;
    const float* ap = sAct + (warp * 16 + g) * PAD + c;
    if (ZERO) {
#pragma unroll
        for (int nt = 0; nt < NT; nt++)
#pragma unroll
            for (int j = 0; j < 4; j++) acc[nt][j] = 0.f;
    }
#pragma unroll
    for (int kt = 0; kt < KT; kt++) {
        uint32_t a[4];
        a[0] = f2tf32(ap[kt * 8]);
        a[1] = f2tf32(ap[8 * PAD + kt * 8]);
        a[2] = f2tf32(ap[kt * 8 + 4]);
        a[3] = f2tf32(ap[8 * PAD + kt * 8 + 4]);
#pragma unroll
        for (int nt = 0; nt < NT; nt++) {
            uint32_t b[2];
            *(float2*)b = *(const float2*)&sB[((kt * NT + nt) * 32 + lane) * 2];
            mma_tf32(acc[nt], a, b);
        }
    }
}

template<int NT, int PAD, bool RELU>
__device__ __forceinline__ void epi_to_smem(float acc[][4], const float* __restrict__ bias,
                                            float* sAct, int warp, int lane) {
    int row = lane >> 2;
    int cb  = (lane & 3) * 2;
    int r1 = warp * 16 + row, r2 = r1 + 8;
#pragma unroll
    for (int nt = 0; nt < NT; nt++) {
        int f = nt * 8 + cb;
        float bx = __ldg(bias + f), by = __ldg(bias + f + 1);
        float2 v1 = make_float2(acc[nt][0] + bx, acc[nt][1] + by);
        float2 v2 = make_float2(acc[nt][2] + bx, acc[nt][3] + by);
        if (RELU) {
            v1.x = fmaxf(v1.x, 0.f); v1.y = fmaxf(v1.y, 0.f);
            v2.x = fmaxf(v2.x, 0.f); v2.y = fmaxf(v2.y, 0.f);
        }
        *(float2*)&sAct[r1 * PAD + f] = v1;
        *(float2*)&sAct[r2 * PAD + f] = v2;
    }
}

template<int NT, int NF, bool RELU>
__device__ __forceinline__ void epi_to_gmem(float acc[][4], const float* __restrict__ bias,
                                            float* __restrict__ Y, int n0, int N,
                                            int warp, int lane) {
    int row = lane >> 2;
    int cb  = (lane & 3) * 2;
    int gn1 = n0 + warp * 16 + row;
    int gn2 = gn1 + 8;
#pragma unroll
    for (int nt = 0; nt < NT; nt++) {
        int f = nt * 8 + cb;
        float bx = __ldg(bias + f), by = __ldg(bias + f + 1);
        float2 v1 = make_float2(acc[nt][0] + bx, acc[nt][1] + by);
        float2 v2 = make_float2(acc[nt][2] + bx, acc[nt][3] + by);
        if (RELU) {
            v1.x = fmaxf(v1.x, 0.f); v1.y = fmaxf(v1.y, 0.f);
            v2.x = fmaxf(v2.x, 0.f); v2.y = fmaxf(v2.y, 0.f);
        }
        if (gn1 < N) *(float2*)&Y[(size_t)gn1 * NF + f] = v1;
        if (gn2 < N) *(float2*)&Y[(size_t)gn2 * NF + f] = v2;
    }
}

// ---------------- lin1: g_h1 = x @ W^T + b  (128 -> 64) ----------------
// Plain-layout sAct chunk (PAD 68), A read direct in MMA.
__global__ void __launch_bounds__(256)
lin1_mma(const float* __restrict__ X, const float* __restrict__ W,
         const float* __restrict__ bias, int N)
{
    constexpr int NT = 8;
    constexpr int PAD = 68;
    extern __shared__ float sm[];
    float* sAct  = sm;                           // 128*68 floats
    uint32_t* sB = (uint32_t*)(sm + 128 * PAD);  // 16*8*64 = 8192 u32

    int t = threadIdx.x, warp = t >> 5, lane = t & 31;
    int n0 = blockIdx.x * 128;

    stage_B<128, NT>(W, sB, t);

    float acc[NT][4];
#pragma unroll
    for (int nt = 0; nt < NT; nt++)
#pragma unroll
        for (int j = 0; j < 4; j++) acc[nt][j] = 0.f;

    int g = lane >> 2, c = lane & 3;
    const float* ap = sAct + (warp * 16 + g) * PAD + c;

    for (int ch = 0; ch < 2; ch++) {
        if (ch) __syncthreads();
        // stage X chunk plain (coalesced float4)
        for (int i = t; i < 128 * 16; i += 256) {
            int n = i >> 4, q = i & 15;
            int gn = n0 + n;
            float4 v = (gn < N) ? *(const float4*)&X[(size_t)gn * 128 + ch * 64 + q * 4]
                                : make_float4(0.f, 0.f, 0.f, 0.f);
            *(float4*)&sAct[n * PAD + q * 4] = v;
        }
        __syncthreads();
#pragma unroll
        for (int kt = 0; kt < 8; kt++) {
            uint32_t a[4];
            a[0] = f2tf32(ap[kt * 8]);
            a[1] = f2tf32(ap[8 * PAD + kt * 8]);
            a[2] = f2tf32(ap[kt * 8 + 4]);
            a[3] = f2tf32(ap[8 * PAD + kt * 8 + 4]);
#pragma unroll
            for (int nt = 0; nt < NT; nt++) {
                uint32_t b[2];
                *(float2*)b = *(const float2*)&sB[(((ch * 8 + kt) * NT + nt) * 32 + lane) * 2];
                mma_tf32(acc[nt], a, b);
            }
        }
    }
    epi_to_gmem<NT, 64, false>(acc, bias, g_h1, n0, N, warp, lane);
}

// ---------------- fused mid-MLP (no sF: 51.2KB smem, 4 blk/SM) ----------------
__global__ void __launch_bounds__(256)
fused_mlp1(const float* __restrict__ W1, const float* __restrict__ b1,
           const float* __restrict__ W2, const float* __restrict__ b2,
           const float* __restrict__ W3, const float* __restrict__ b3, int N)
{
    constexpr int PAD = 68;
    extern __shared__ float sm[];
    float* sAct  = sm;                           // 128*68 floats = 34816 B
    uint32_t* sB = (uint32_t*)(sm + 128 * PAD);  // 8*8*64 = 4096 u32 = 16384 B

    int t = threadIdx.x, warp = t >> 5, lane = t & 31;
    int n0 = blockIdx.x * 128;

    stage_B<64, 8>(W1, sB, t);
    for (int i = t; i < 128 * 16; i += 256) {
        int n = i >> 4, q = i & 15;
        int gn = n0 + n;
        float4 v = (gn < N) ? *(const float4*)&g_agg1[(size_t)gn * 64 + q * 4]
                            : make_float4(0.f, 0.f, 0.f, 0.f);
        v.x = fmaxf(v.x, 0.f); v.y = fmaxf(v.y, 0.f);
        v.z = fmaxf(v.z, 0.f); v.w = fmaxf(v.w, 0.f);
        *(float4*)&sAct[n * PAD + q * 4] = v;
    }
    __syncthreads();

    float acc[8][4];

    // stage 1
    mma_direct<64, 8, PAD, true>(sAct, sB, acc, warp, lane);
    __syncthreads();
    epi_to_smem<8, PAD, true>(acc, b1, sAct, warp, lane);
    stage_B<64, 8>(W2, sB, t);
    __syncthreads();

    // stage 2
    mma_direct<64, 8, PAD, true>(sAct, sB, acc, warp, lane);
    __syncthreads();
    epi_to_smem<8, PAD, true>(acc, b2, sAct, warp, lane);
    stage_B<64, 5>(W3, sB, t);
    __syncthreads();

    // stage 3 -> g_h2 (64 -> 40)
    mma_direct<64, 5, PAD, true>(sAct, sB, acc, warp, lane);
    epi_to_gmem<5, 40, false>(acc, b3, g_h2, n0, N, warp, lane);
}

// ---------------- fused final MLP (no sF: 35.3KB smem) ----------------
__global__ void __launch_bounds__(256)
fused_mlp2(const float* __restrict__ W1, const float* __restrict__ b1,
           const float* __restrict__ W2, const float* __restrict__ b2,
           float* __restrict__ out, int N)
{
    constexpr int PAD = 44;
    extern __shared__ float sm[];
    float* sAct   = sm;                             // 128*44 floats
    uint32_t* sB1 = (uint32_t*)(sm + 128 * PAD);    // 5*5*64 = 1600 u32
    uint32_t* sB2 = sB1 + 1600;

    int t = threadIdx.x, warp = t >> 5, lane = t & 31;
    int n0 = blockIdx.x * 128;

    stage_B<40, 5>(W1, sB1, t);
    stage_B<40, 5>(W2, sB2, t);

    for (int i = t; i < 128 * 10; i += 256) {
        int n = i / 10, q = i - n * 10;
        int gn = n0 + n;
        float4 v = (gn < N) ? *(const float4*)&g_agg2[(size_t)gn * 40 + q * 4]
                            : make_float4(0.f, 0.f, 0.f, 0.f);
        v.x = fmaxf(v.x, 0.f); v.y = fmaxf(v.y, 0.f);
        v.z = fmaxf(v.z, 0.f); v.w = fmaxf(v.w, 0.f);
        *(float4*)&sAct[n * PAD + q * 4] = v;
    }
    __syncthreads();

    float acc[5][4];

    mma_direct<40, 5, PAD, true>(sAct, sB1, acc, warp, lane);
    __syncthreads();
    epi_to_smem<5, PAD, true>(acc, b1, sAct, warp, lane);
    __syncthreads();

    mma_direct<40, 5, PAD, true>(sAct, sB2, acc, warp, lane);
    epi_to_gmem<5, 40, false>(acc, b2, out, n0, N, warp, lane);
}

// ---------------- launch ----------------
extern "C" void kernel_launch(void* const* d_in, const int* in_sizes, int n_in,
                              void* d_out, int out_size) {
    const float*     x   = (const float*)d_in[0];
    const long long* idx = (const long long*)d_in[1];
    const float* w1_lin = (const float*)d_in[2];
    const float* b1_lin = (const float*)d_in[3];
    const float* w1_o1  = (const float*)d_in[4];
    const float* b1_o1  = (const float*)d_in[5];
    const float* w1_o2  = (const float*)d_in[6];
    const float* b1_o2  = (const float*)d_in[7];
    const float* w2_lin = (const float*)d_in[8];
    const float* b2_lin = (const float*)d_in[9];
    const float* w2_o1  = (const float*)d_in[10];
    const float* b2_o1  = (const float*)d_in[11];
    const float* w2_o2  = (const float*)d_in[12];
    const float* b2_o2  = (const float*)d_in[13];
    float* out = (float*)d_out;

    int N = in_sizes[0] / 128;
    int E = in_sizes[1] / 2;

    const int SM_LIN1 = (128 * 68) * 4 + 8192 * 4;        // 67584
    const int SM_MLP1 = (128 * 68) * 4 + 4096 * 4;        // 51200
    const int SM_MLP2 = (128 * 44) * 4 + 3200 * 4;        // 35328

    cudaFuncSetAttribute(lin1_mma,   cudaFuncAttributeMaxDynamicSharedMemorySize, SM_LIN1);
    cudaFuncSetAttribute(fused_mlp1, cudaFuncAttributeMaxDynamicSharedMemorySize, SM_MLP1);
    cudaFuncSetAttribute(fused_mlp2, cudaFuncAttributeMaxDynamicSharedMemorySize, SM_MLP2);

    static cudaStream_t s2 = nullptr;
    static cudaEvent_t evF = nullptr, evJ = nullptr;
    if (s2 == nullptr) {
        cudaStreamCreateWithFlags(&s2, cudaStreamNonBlocking);
        cudaEventCreateWithFlags(&evF, cudaEventDisableTiming);
        cudaEventCreateWithFlags(&evJ, cudaEventDisableTiming);
    }
    void *degPtr = nullptr, *ovfPtr = nullptr;
    cudaGetSymbolAddress(&degPtr, g_deg);
    cudaGetSymbolAddress(&ovfPtr, g_ovf_cnt);

    int gemmBlocks = (N + 127) / 128;

    // fork: CSR build on side stream, concurrent with lin1 on main stream
    cudaEventRecord(evF, 0);
    cudaStreamWaitEvent(s2, evF, 0);
    cudaMemsetAsync(degPtr, 0, (size_t)N * sizeof(int), s2);
    cudaMemsetAsync(ovfPtr, 0, sizeof(int), s2);
    detect_idx_kernel<<<1, 32, 0, s2>>>(idx, E, (long long)N);
    csr_fill_kernel<<<(E + 255) / 256, 256, 0, s2>>>(idx, E);
    cudaEventRecord(evJ, s2);

    lin1_mma<<<gemmBlocks, 256, SM_LIN1>>>(x, w1_lin, b1_lin, N);

    cudaStreamWaitEvent(0, evJ, 0);

    // layer 1: gather (2 nodes/warp) + fused mlp
    int w64 = (N + 1) / 2;
    gather64_kernel<<<(w64 + 7) / 8, 256>>>(N);
    ovf_scatter_kernel<64, 1><<<64, 128>>>();
    fused_mlp1<<<gemmBlocks, 256, SM_MLP1>>>(w1_o1, b1_o1, w1_o2, b1_o2,
                                             w2_lin, b2_lin, N);

    // layer 2: gather (3 nodes/warp) + fused mlp
    int w40 = (N + 2) / 3;
    gather40_kernel<<<(w40 + 7) / 8, 256>>>(N);
    ovf_scatter_kernel<40, 2><<<64, 128>>>();
    fused_mlp2<<<gemmBlocks, 256, SM_MLP2>>>(w2_o1, b2_o1, w2_o2, b2_o2, out, N);
}